// round 3
// baseline (speedup 1.0000x reference)
#include <cuda_runtime.h>
#include <cstdint>
#include <cstddef>

#define B_   4
#define T_   2048
#define DM   1024
#define H_   16
#define DH   64
#define NTOK (B_ * T_)   // 8192

// Scratch (allocation-free rule: __device__ globals)
__device__ float g_qkv[(size_t)NTOK * 3 * DM];   // [b,t, 3, H, Dh] = [8192][3072]
__device__ float g_attn[(size_t)NTOK * DM];      // [b,t, H, Dh]    = [8192][1024]

// ---------------------------------------------------------------------------
// Classic 128x128x8 fp32 SGEMM, row-major A[M,K] * B[K,N] -> C[M,N].
// 256 threads, 8x8 per thread (two 4-wide subtiles per dim for conflict-free
// LDS.128). M,N multiples of 128; K multiple of 8.
// ---------------------------------------------------------------------------
__global__ __launch_bounds__(256) void sgemm128(const float* __restrict__ A,
                                                const float* __restrict__ Bm,
                                                float* __restrict__ C,
                                                int M, int N, int K)
{
    __shared__ float As[8][128];   // transposed A tile
    __shared__ float Bs[8][128];

    const int tid  = threadIdx.x;
    const int tx   = tid & 15;
    const int ty   = tid >> 4;
    const int row0 = blockIdx.y << 7;
    const int col0 = blockIdx.x << 7;

    // A tile load: 128 rows x 8 cols; thread pairs cover 32B of one row.
    const int arow = tid >> 1;
    const int acol = (tid & 1) << 2;
    // B tile load: 8 rows x 128 cols, one float4 per thread, fully coalesced.
    const int brow = tid >> 5;
    const int bcol = (tid & 31) << 2;

    const float* Ap = A  + (size_t)(row0 + arow) * K + acol;
    const float* Bp = Bm + (size_t)brow * N + col0 + bcol;

    float acc[8][8];
#pragma unroll
    for (int i = 0; i < 8; ++i)
#pragma unroll
        for (int j = 0; j < 8; ++j) acc[i][j] = 0.f;

    for (int k0 = 0; k0 < K; k0 += 8) {
        float4 av = *(const float4*)(Ap + k0);
        float4 bv = *(const float4*)(Bp + (size_t)k0 * N);
        As[acol + 0][arow] = av.x;
        As[acol + 1][arow] = av.y;
        As[acol + 2][arow] = av.z;
        As[acol + 3][arow] = av.w;
        *(float4*)&Bs[brow][bcol] = bv;
        __syncthreads();
#pragma unroll
        for (int k = 0; k < 8; ++k) {
            float a[8], b[8];
            *(float4*)&a[0] = *(const float4*)&As[k][(ty << 2)];
            *(float4*)&a[4] = *(const float4*)&As[k][64 + (ty << 2)];
            *(float4*)&b[0] = *(const float4*)&Bs[k][(tx << 2)];
            *(float4*)&b[4] = *(const float4*)&Bs[k][64 + (tx << 2)];
#pragma unroll
            for (int i = 0; i < 8; ++i)
#pragma unroll
                for (int j = 0; j < 8; ++j)
                    acc[i][j] = fmaf(a[i], b[j], acc[i][j]);
        }
        __syncthreads();
    }

#pragma unroll
    for (int ih = 0; ih < 2; ++ih)
#pragma unroll
        for (int i = 0; i < 4; ++i) {
            const int ii = ih * 4 + i;
            float* Cp = C + (size_t)(row0 + ih * 64 + (ty << 2) + i) * N + col0;
            *(float4*)(Cp + (tx << 2)) =
                make_float4(acc[ii][0], acc[ii][1], acc[ii][2], acc[ii][3]);
            *(float4*)(Cp + 64 + (tx << 2)) =
                make_float4(acc[ii][4], acc[ii][5], acc[ii][6], acc[ii][7]);
        }
}

// ---------------------------------------------------------------------------
// Causal flash attention. One CTA per (q-tile of 64, head, batch).
// 256 threads as 16x16 grid; each thread owns a 4x4 fragment of the 64x64
// score tile and a 4x4 fragment of the 64-wide output accumulator.
// Online softmax with shfl reductions across the 16 threads sharing a row.
// smem: Qs[64][64] + Kt[64][68] (transposed, padded) + Vs[64][64] + Ps[64][64]
//       = 66560 bytes dynamic.
// ---------------------------------------------------------------------------
__global__ __launch_bounds__(256) void attn64_kernel(const float* __restrict__ qkv,
                                                     float* __restrict__ out)
{
    extern __shared__ float sm[];
    float* Qs = sm;                    // [64][64]  stride 64
    float* Kt = sm + 4096;             // [k=64][r=64] stride 68 (transposed K)
    float* Vs = Kt + 64 * 68;          // [64][64]  stride 64
    float* Ps = Vs + 4096;             // [64][64]  stride 64

    const int tid = threadIdx.x;
    const int tx  = tid & 15;          // column group
    const int ty  = tid >> 4;          // row group
    const int qt  = blockIdx.x;
    const int h   = blockIdx.y;
    const int b   = blockIdx.z;
    const int q0  = qt << 6;

    const float* bb = qkv + (size_t)b * (T_ * 3 * DM) + h * DH;

    // Load Q tile [64 tokens][64 dims], row-major, coalesced float4
    for (int i = tid; i < 64 * 16; i += 256) {
        const int r  = i >> 4;
        const int c4 = (i & 15) << 2;
        *(float4*)(Qs + r * 64 + c4) =
            *(const float4*)(bb + (size_t)(q0 + r) * (3 * DM) + c4);
    }

    float m[4], l[4], acc[4][4];
#pragma unroll
    for (int i = 0; i < 4; ++i) {
        m[i] = -1e30f; l[i] = 0.f;
#pragma unroll
        for (int j = 0; j < 4; ++j) acc[i][j] = 0.f;
    }

    for (int kt = 0; kt <= qt; ++kt) {
        const int k0 = kt << 6;
        __syncthreads();  // prior-iteration reads of Kt/Vs/Ps complete

        // K tile, transposed into Kt[d][r] (stride 68 -> conflict-free STS.128
        // and LDS.128). Each thread: 4 coalesced global loads (same d, tokens
        // r..r+3), one float4 smem store.
        {
            const int d = tid & 63;
            const float* kcol = bb + DM + d;
#pragma unroll
            for (int it = 0; it < 4; ++it) {
                const int r = (((tid >> 6) + (it << 2)) << 2);   // 0,4,...,60
                const float* kp = kcol + (size_t)(k0 + r) * (3 * DM);
                float4 kv;
                kv.x = kp[0];
                kv.y = kp[3 * DM];
                kv.z = kp[6 * DM];
                kv.w = kp[9 * DM];
                *(float4*)(Kt + d * 68 + r) = kv;
            }
        }
        // V tile row-major
        for (int i = tid; i < 64 * 16; i += 256) {
            const int r  = i >> 4;
            const int c4 = (i & 15) << 2;
            *(float4*)(Vs + r * 64 + c4) =
                *(const float4*)(bb + 2 * DM + (size_t)(k0 + r) * (3 * DM) + c4);
        }
        __syncthreads();

        // S = Q @ K^T  (4x4 fragment per thread), k in chunks of 4 (float4)
        float s[4][4];
#pragma unroll
        for (int i = 0; i < 4; ++i)
#pragma unroll
            for (int j = 0; j < 4; ++j) s[i][j] = 0.f;

#pragma unroll 4
        for (int k4 = 0; k4 < 64; k4 += 4) {
            float qa[4][4], kb[4][4];
#pragma unroll
            for (int i = 0; i < 4; ++i)
                *(float4*)qa[i] = *(const float4*)(Qs + ((ty << 2) + i) * 64 + k4);
#pragma unroll
            for (int kk = 0; kk < 4; ++kk)
                *(float4*)kb[kk] = *(const float4*)(Kt + (k4 + kk) * 68 + (tx << 2));
#pragma unroll
            for (int kk = 0; kk < 4; ++kk)
#pragma unroll
                for (int i = 0; i < 4; ++i)
#pragma unroll
                    for (int j = 0; j < 4; ++j)
                        s[i][j] = fmaf(qa[i][kk], kb[kk][j], s[i][j]);
        }

        // scale + causal mask + online softmax
        const bool diag = (kt == qt);
#pragma unroll
        for (int i = 0; i < 4; ++i) {
            const int ri = (ty << 2) + i;
#pragma unroll
            for (int j = 0; j < 4; ++j) {
                float v = s[i][j] * 0.125f;     // 1/sqrt(64)
                if (diag && ((tx << 2) + j) > ri) v = -1e30f;
                s[i][j] = v;
            }
            float rm = fmaxf(fmaxf(s[i][0], s[i][1]), fmaxf(s[i][2], s[i][3]));
            rm = fmaxf(rm, __shfl_xor_sync(0xffffffffu, rm, 1, 16));
            rm = fmaxf(rm, __shfl_xor_sync(0xffffffffu, rm, 2, 16));
            rm = fmaxf(rm, __shfl_xor_sync(0xffffffffu, rm, 4, 16));
            rm = fmaxf(rm, __shfl_xor_sync(0xffffffffu, rm, 8, 16));
            const float mn   = fmaxf(m[i], rm);
            const float corr = __expf(m[i] - mn);
            m[i] = mn;
            float rs = 0.f;
#pragma unroll
            for (int j = 0; j < 4; ++j) {
                const float p = __expf(s[i][j] - mn);
                s[i][j] = p;
                rs += p;
            }
            rs += __shfl_xor_sync(0xffffffffu, rs, 1, 16);
            rs += __shfl_xor_sync(0xffffffffu, rs, 2, 16);
            rs += __shfl_xor_sync(0xffffffffu, rs, 4, 16);
            rs += __shfl_xor_sync(0xffffffffu, rs, 8, 16);
            l[i] = l[i] * corr + rs;
#pragma unroll
            for (int j = 0; j < 4; ++j) acc[i][j] *= corr;
        }

        // stage P to smem (conflict-free float4 stores)
#pragma unroll
        for (int i = 0; i < 4; ++i)
            *(float4*)(Ps + ((ty << 2) + i) * 64 + (tx << 2)) =
                make_float4(s[i][0], s[i][1], s[i][2], s[i][3]);
        __syncthreads();

        // O += P @ V
#pragma unroll 4
        for (int k4 = 0; k4 < 64; k4 += 4) {
            float pa[4][4], vb[4][4];
#pragma unroll
            for (int i = 0; i < 4; ++i)
                *(float4*)pa[i] = *(const float4*)(Ps + ((ty << 2) + i) * 64 + k4);
#pragma unroll
            for (int kk = 0; kk < 4; ++kk)
                *(float4*)vb[kk] = *(const float4*)(Vs + (k4 + kk) * 64 + (tx << 2));
#pragma unroll
            for (int kk = 0; kk < 4; ++kk)
#pragma unroll
                for (int i = 0; i < 4; ++i)
#pragma unroll
                    for (int j = 0; j < 4; ++j)
                        acc[i][j] = fmaf(pa[i][kk], vb[kk][j], acc[i][j]);
        }
    }

    // epilogue: divide by l, write [b, t, h, d]
    float* ob = out + ((size_t)(b * T_ + q0)) * DM + h * DH;
#pragma unroll
    for (int i = 0; i < 4; ++i) {
        const float inv = 1.f / l[i];
        *(float4*)(ob + (size_t)((ty << 2) + i) * DM + (tx << 2)) =
            make_float4(acc[i][0] * inv, acc[i][1] * inv,
                        acc[i][2] * inv, acc[i][3] * inv);
    }
}

// ---------------------------------------------------------------------------
extern "C" void kernel_launch(void* const* d_in, const int* in_sizes, int n_in,
                              void* d_out, int out_size)
{
    const float* x     = (const float*)d_in[0];   // [4,2048,1024]
    const float* w_qkv = (const float*)d_in[1];   // [1024,3072]
    const float* w_out = (const float*)d_in[2];   // [1024,1024]
    float* out = (float*)d_out;                   // [4,2048,1024]

    float *qkv, *attn;
    cudaGetSymbolAddress((void**)&qkv,  g_qkv);
    cudaGetSymbolAddress((void**)&attn, g_attn);

    const int attn_smem = (4096 + 64 * 68 + 4096 + 4096) * 4;  // 66560 B
    cudaFuncSetAttribute(attn64_kernel,
                         cudaFuncAttributeMaxDynamicSharedMemorySize, attn_smem);

    // 1) qkv = x @ w_qkv           (8192 x 3072 x 1024)
    sgemm128<<<dim3((3 * DM) / 128, NTOK / 128), 256>>>(x, w_qkv, qkv,
                                                        NTOK, 3 * DM, DM);
    // 2) causal flash attention    (per (qtile, head, batch))
    attn64_kernel<<<dim3(T_ / 64, H_, B_), 256, attn_smem>>>(qkv, attn);
    // 3) out = attn @ w_out        (8192 x 1024 x 1024)
    sgemm128<<<dim3(DM / 128, NTOK / 128), 256>>>(attn, w_out, out,
                                                  NTOK, DM, DM);
}

// round 4
// speedup vs baseline: 1.6631x; 1.6631x over previous
#include <cuda_runtime.h>
#include <cstdint>
#include <cstddef>

#define B_   4
#define T_   2048
#define DM   1024
#define H_   16
#define DH   64
#define NTOK (B_ * T_)   // 8192

// Scratch (allocation-free rule: __device__ globals)
__device__ float g_qkv[(size_t)NTOK * 3 * DM];   // [b,t, 3, H, Dh]
__device__ float g_attn[(size_t)NTOK * DM];      // [b,t, H, Dh]

// ---------------------------------------------------------------------------
// TF32 tensor-core GEMM: C[M,N] = A[M,K] * B[K,N], all row-major fp32.
// CTA tile 128x128, K-chunk 32, 256 threads (8 warps, warp tile 32x64).
// mma.sync.m16n8k8.tf32 with cvt.rna rounding. cp.async double buffer.
// Smem pads (A stride 36, B stride 136) make all fragment LDS conflict-free.
// ---------------------------------------------------------------------------
#define ASTR 36
#define BSTR 136
#define ASZ  (128 * ASTR)           // floats per A buffer
#define BSZ  (32 * BSTR)            // floats per B buffer
#define GEMM_SMEM ((2 * ASZ + 2 * BSZ) * 4)   // 71680 bytes

__device__ __forceinline__ void cpa16(float* s, const float* g) {
    uint32_t sa = (uint32_t)__cvta_generic_to_shared(s);
    asm volatile("cp.async.cg.shared.global [%0], [%1], 16;\n" :: "r"(sa), "l"(g));
}
__device__ __forceinline__ void cpa_commit() {
    asm volatile("cp.async.commit_group;\n");
}
__device__ __forceinline__ void cpa_wait0() {
    asm volatile("cp.async.wait_group 0;\n");
}
__device__ __forceinline__ uint32_t f2tf32(float x) {
    uint32_t r;
    asm("cvt.rna.tf32.f32 %0, %1;" : "=r"(r) : "f"(x));
    return r;
}

__global__ __launch_bounds__(256) void tf32_gemm(const float* __restrict__ A,
                                                 const float* __restrict__ Bm,
                                                 float* __restrict__ C,
                                                 int M, int N, int K)
{
    extern __shared__ float sm[];
    float* As = sm;                 // [2][128][ASTR]
    float* Bs = sm + 2 * ASZ;       // [2][32][BSTR]

    const int tid  = threadIdx.x;
    const int lane = tid & 31;
    const int warp = tid >> 5;
    const int wm   = warp >> 1;     // 0..3  (warp row: 32 rows each)
    const int wn   = warp & 1;      // 0..1  (warp col: 64 cols each)
    const int lr   = lane >> 2;     // 0..7
    const int lc   = lane & 3;      // 0..3
    const int row0 = blockIdx.y << 7;
    const int col0 = blockIdx.x << 7;

    // global->smem load indices
    const int ar = tid >> 3;              // 0..31 (A: +it*32)
    const int ac = (tid & 7) << 2;        // 0..28
    const int br = tid >> 5;              // 0..7  (B: +it*8)
    const int bc = (tid & 31) << 2;       // 0..124

    float acc[2][8][4];
#pragma unroll
    for (int mi = 0; mi < 2; ++mi)
#pragma unroll
        for (int ni = 0; ni < 8; ++ni)
#pragma unroll
            for (int r = 0; r < 4; ++r) acc[mi][ni][r] = 0.f;

    const int nch = K >> 5;

    // prologue: load chunk 0 into buffer 0
    {
        const float* Ag = A + (size_t)(row0 + ar) * K + ac;
        const float* Bg = Bm + (size_t)br * N + col0 + bc;
#pragma unroll
        for (int it = 0; it < 4; ++it)
            cpa16(As + (ar + it * 32) * ASTR + ac, Ag + (size_t)(it * 32) * K);
#pragma unroll
        for (int it = 0; it < 4; ++it)
            cpa16(Bs + (br + it * 8) * BSTR + bc, Bg + (size_t)(it * 8) * N);
        cpa_commit();
    }

    for (int c = 0; c < nch; ++c) {
        cpa_wait0();
        __syncthreads();

        const int cb = c & 1;
        if (c + 1 < nch) {
            const int nb = (c + 1) & 1;
            const int k0 = (c + 1) << 5;
            const float* Ag = A + (size_t)(row0 + ar) * K + k0 + ac;
            const float* Bg = Bm + (size_t)(k0 + br) * N + col0 + bc;
#pragma unroll
            for (int it = 0; it < 4; ++it)
                cpa16(As + nb * ASZ + (ar + it * 32) * ASTR + ac,
                      Ag + (size_t)(it * 32) * K);
#pragma unroll
            for (int it = 0; it < 4; ++it)
                cpa16(Bs + nb * BSZ + (br + it * 8) * BSTR + bc,
                      Bg + (size_t)(it * 8) * N);
            cpa_commit();
        }

        const float* as = As + cb * ASZ;
        const float* bs = Bs + cb * BSZ;

#pragma unroll
        for (int kk = 0; kk < 32; kk += 8) {
            uint32_t af[2][4], bf[8][2];
#pragma unroll
            for (int mi = 0; mi < 2; ++mi) {
                const int mrow = (wm << 5) + (mi << 4) + lr;
                const float* ap = as + mrow * ASTR + kk + lc;
                af[mi][0] = f2tf32(ap[0]);
                af[mi][1] = f2tf32(ap[8 * ASTR]);
                af[mi][2] = f2tf32(ap[4]);
                af[mi][3] = f2tf32(ap[8 * ASTR + 4]);
            }
#pragma unroll
            for (int ni = 0; ni < 8; ++ni) {
                const int ncol = (wn << 6) + (ni << 3) + lr;
                const float* bp = bs + (kk + lc) * BSTR + ncol;
                bf[ni][0] = f2tf32(bp[0]);
                bf[ni][1] = f2tf32(bp[4 * BSTR]);
            }
#pragma unroll
            for (int mi = 0; mi < 2; ++mi)
#pragma unroll
                for (int ni = 0; ni < 8; ++ni) {
                    float* cc = acc[mi][ni];
                    asm volatile(
                        "mma.sync.aligned.m16n8k8.row.col.f32.tf32.tf32.f32 "
                        "{%0,%1,%2,%3}, {%4,%5,%6,%7}, {%8,%9}, {%0,%1,%2,%3};"
                        : "+f"(cc[0]), "+f"(cc[1]), "+f"(cc[2]), "+f"(cc[3])
                        : "r"(af[mi][0]), "r"(af[mi][1]),
                          "r"(af[mi][2]), "r"(af[mi][3]),
                          "r"(bf[ni][0]), "r"(bf[ni][1]));
                }
        }
    }

    // epilogue: fragment layout -> C (float2 stores)
#pragma unroll
    for (int mi = 0; mi < 2; ++mi) {
        const int row = row0 + (wm << 5) + (mi << 4) + lr;
#pragma unroll
        for (int ni = 0; ni < 8; ++ni) {
            const int col = col0 + (wn << 6) + (ni << 3) + (lc << 1);
            const float* cc = acc[mi][ni];
            *(float2*)(C + (size_t)row * N + col)       = make_float2(cc[0], cc[1]);
            *(float2*)(C + (size_t)(row + 8) * N + col) = make_float2(cc[2], cc[3]);
        }
    }
}

// ---------------------------------------------------------------------------
// Causal flash attention (unchanged from R3 baseline, exact fp32).
// One CTA per (q-tile of 64, head, batch); 256 threads, 4x4 fragments.
// ---------------------------------------------------------------------------
__global__ __launch_bounds__(256) void attn64_kernel(const float* __restrict__ qkv,
                                                     float* __restrict__ out)
{
    extern __shared__ float smm[];
    float* Qs = smm;                   // [64][64]
    float* Kt = smm + 4096;            // [64][68] transposed K
    float* Vs = Kt + 64 * 68;          // [64][64]
    float* Ps = Vs + 4096;             // [64][64]

    const int tid = threadIdx.x;
    const int tx  = tid & 15;
    const int ty  = tid >> 4;
    const int qt  = blockIdx.x;
    const int h   = blockIdx.y;
    const int b   = blockIdx.z;
    const int q0  = qt << 6;

    const float* bb = qkv + (size_t)b * (T_ * 3 * DM) + h * DH;

    for (int i = tid; i < 64 * 16; i += 256) {
        const int r  = i >> 4;
        const int c4 = (i & 15) << 2;
        *(float4*)(Qs + r * 64 + c4) =
            *(const float4*)(bb + (size_t)(q0 + r) * (3 * DM) + c4);
    }

    float m[4], l[4], acc[4][4];
#pragma unroll
    for (int i = 0; i < 4; ++i) {
        m[i] = -1e30f; l[i] = 0.f;
#pragma unroll
        for (int j = 0; j < 4; ++j) acc[i][j] = 0.f;
    }

    for (int kt = 0; kt <= qt; ++kt) {
        const int k0 = kt << 6;
        __syncthreads();

        {
            const int d = tid & 63;
            const float* kcol = bb + DM + d;
#pragma unroll
            for (int it = 0; it < 4; ++it) {
                const int r = (((tid >> 6) + (it << 2)) << 2);
                const float* kp = kcol + (size_t)(k0 + r) * (3 * DM);
                float4 kv;
                kv.x = kp[0];
                kv.y = kp[3 * DM];
                kv.z = kp[6 * DM];
                kv.w = kp[9 * DM];
                *(float4*)(Kt + d * 68 + r) = kv;
            }
        }
        for (int i = tid; i < 64 * 16; i += 256) {
            const int r  = i >> 4;
            const int c4 = (i & 15) << 2;
            *(float4*)(Vs + r * 64 + c4) =
                *(const float4*)(bb + 2 * DM + (size_t)(k0 + r) * (3 * DM) + c4);
        }
        __syncthreads();

        float s[4][4];
#pragma unroll
        for (int i = 0; i < 4; ++i)
#pragma unroll
            for (int j = 0; j < 4; ++j) s[i][j] = 0.f;

#pragma unroll 4
        for (int k4 = 0; k4 < 64; k4 += 4) {
            float qa[4][4], kb[4][4];
#pragma unroll
            for (int i = 0; i < 4; ++i)
                *(float4*)qa[i] = *(const float4*)(Qs + ((ty << 2) + i) * 64 + k4);
#pragma unroll
            for (int kk = 0; kk < 4; ++kk)
                *(float4*)kb[kk] = *(const float4*)(Kt + (k4 + kk) * 68 + (tx << 2));
#pragma unroll
            for (int kk = 0; kk < 4; ++kk)
#pragma unroll
                for (int i = 0; i < 4; ++i)
#pragma unroll
                    for (int j = 0; j < 4; ++j)
                        s[i][j] = fmaf(qa[i][kk], kb[kk][j], s[i][j]);
        }

        const bool diag = (kt == qt);
#pragma unroll
        for (int i = 0; i < 4; ++i) {
            const int ri = (ty << 2) + i;
#pragma unroll
            for (int j = 0; j < 4; ++j) {
                float v = s[i][j] * 0.125f;
                if (diag && ((tx << 2) + j) > ri) v = -1e30f;
                s[i][j] = v;
            }
            float rm = fmaxf(fmaxf(s[i][0], s[i][1]), fmaxf(s[i][2], s[i][3]));
            rm = fmaxf(rm, __shfl_xor_sync(0xffffffffu, rm, 1, 16));
            rm = fmaxf(rm, __shfl_xor_sync(0xffffffffu, rm, 2, 16));
            rm = fmaxf(rm, __shfl_xor_sync(0xffffffffu, rm, 4, 16));
            rm = fmaxf(rm, __shfl_xor_sync(0xffffffffu, rm, 8, 16));
            const float mn   = fmaxf(m[i], rm);
            const float corr = __expf(m[i] - mn);
            m[i] = mn;
            float rs = 0.f;
#pragma unroll
            for (int j = 0; j < 4; ++j) {
                const float p = __expf(s[i][j] - mn);
                s[i][j] = p;
                rs += p;
            }
            rs += __shfl_xor_sync(0xffffffffu, rs, 1, 16);
            rs += __shfl_xor_sync(0xffffffffu, rs, 2, 16);
            rs += __shfl_xor_sync(0xffffffffu, rs, 4, 16);
            rs += __shfl_xor_sync(0xffffffffu, rs, 8, 16);
            l[i] = l[i] * corr + rs;
#pragma unroll
            for (int j = 0; j < 4; ++j) acc[i][j] *= corr;
        }

#pragma unroll
        for (int i = 0; i < 4; ++i)
            *(float4*)(Ps + ((ty << 2) + i) * 64 + (tx << 2)) =
                make_float4(s[i][0], s[i][1], s[i][2], s[i][3]);
        __syncthreads();

#pragma unroll 4
        for (int k4 = 0; k4 < 64; k4 += 4) {
            float pa[4][4], vb[4][4];
#pragma unroll
            for (int i = 0; i < 4; ++i)
                *(float4*)pa[i] = *(const float4*)(Ps + ((ty << 2) + i) * 64 + k4);
#pragma unroll
            for (int kk = 0; kk < 4; ++kk)
                *(float4*)vb[kk] = *(const float4*)(Vs + (k4 + kk) * 64 + (tx << 2));
#pragma unroll
            for (int kk = 0; kk < 4; ++kk)
#pragma unroll
                for (int i = 0; i < 4; ++i)
#pragma unroll
                    for (int j = 0; j < 4; ++j)
                        acc[i][j] = fmaf(pa[i][kk], vb[kk][j], acc[i][j]);
        }
    }

    float* ob = out + ((size_t)(b * T_ + q0)) * DM + h * DH;
#pragma unroll
    for (int i = 0; i < 4; ++i) {
        const float inv = 1.f / l[i];
        *(float4*)(ob + (size_t)((ty << 2) + i) * DM + (tx << 2)) =
            make_float4(acc[i][0] * inv, acc[i][1] * inv,
                        acc[i][2] * inv, acc[i][3] * inv);
    }
}

// ---------------------------------------------------------------------------
extern "C" void kernel_launch(void* const* d_in, const int* in_sizes, int n_in,
                              void* d_out, int out_size)
{
    const float* x     = (const float*)d_in[0];   // [4,2048,1024]
    const float* w_qkv = (const float*)d_in[1];   // [1024,3072]
    const float* w_out = (const float*)d_in[2];   // [1024,1024]
    float* out = (float*)d_out;                   // [4,2048,1024]

    float *qkv, *attn;
    cudaGetSymbolAddress((void**)&qkv,  g_qkv);
    cudaGetSymbolAddress((void**)&attn, g_attn);

    cudaFuncSetAttribute(tf32_gemm,
                         cudaFuncAttributeMaxDynamicSharedMemorySize, GEMM_SMEM);
    const int attn_smem = (4096 + 64 * 68 + 4096 + 4096) * 4;  // 66560 B
    cudaFuncSetAttribute(attn64_kernel,
                         cudaFuncAttributeMaxDynamicSharedMemorySize, attn_smem);

    // 1) qkv = x @ w_qkv           (8192 x 3072 x 1024), tf32 tensor cores
    tf32_gemm<<<dim3((3 * DM) / 128, NTOK / 128), 256, GEMM_SMEM>>>(
        x, w_qkv, qkv, NTOK, 3 * DM, DM);
    // 2) causal flash attention    (exact fp32)
    attn64_kernel<<<dim3(T_ / 64, H_, B_), 256, attn_smem>>>(qkv, attn);
    // 3) out = attn @ w_out        (8192 x 1024 x 1024), tf32 tensor cores
    tf32_gemm<<<dim3(DM / 128, NTOK / 128), 256, GEMM_SMEM>>>(
        attn, w_out, out, NTOK, DM, DM);
}

// round 5
// speedup vs baseline: 2.2540x; 1.3553x over previous
#include <cuda_runtime.h>
#include <cstdint>
#include <cstddef>

#define B_   4
#define T_   2048
#define DM   1024
#define H_   16
#define DH   64
#define NTOK (B_ * T_)   // 8192

// Scratch (allocation-free rule: __device__ globals)
__device__ float g_qkv[(size_t)NTOK * 3 * DM];
__device__ float g_attn[(size_t)NTOK * DM];

__device__ __forceinline__ void cpa16(float* s, const float* g) {
    uint32_t sa = (uint32_t)__cvta_generic_to_shared(s);
    asm volatile("cp.async.cg.shared.global [%0], [%1], 16;\n" :: "r"(sa), "l"(g));
}
__device__ __forceinline__ void cpa_commit() {
    asm volatile("cp.async.commit_group;\n");
}
__device__ __forceinline__ void cpa_wait0() {
    asm volatile("cp.async.wait_group 0;\n");
}
__device__ __forceinline__ uint32_t f2tf32(float x) {
    uint32_t r;
    asm("cvt.rna.tf32.f32 %0, %1;" : "=r"(r) : "f"(x));
    return r;
}
#define MMA_TF32(CC, AF, B0, B1)                                              \
    asm volatile(                                                             \
        "mma.sync.aligned.m16n8k8.row.col.f32.tf32.tf32.f32 "                 \
        "{%0,%1,%2,%3}, {%4,%5,%6,%7}, {%8,%9}, {%0,%1,%2,%3};"               \
        : "+f"((CC)[0]), "+f"((CC)[1]), "+f"((CC)[2]), "+f"((CC)[3])          \
        : "r"((AF)[0]), "r"((AF)[1]), "r"((AF)[2]), "r"((AF)[3]),             \
          "r"(B0), "r"(B1))

// ---------------------------------------------------------------------------
// TF32 tensor-core GEMM (unchanged from R4): 128x128 CTA tile, k-chunk 32,
// 256 threads, cp.async double buffer.
// ---------------------------------------------------------------------------
#define ASTR 36
#define BSTR 136
#define ASZ  (128 * ASTR)
#define BSZ  (32 * BSTR)
#define GEMM_SMEM ((2 * ASZ + 2 * BSZ) * 4)

__global__ __launch_bounds__(256) void tf32_gemm(const float* __restrict__ A,
                                                 const float* __restrict__ Bm,
                                                 float* __restrict__ C,
                                                 int M, int N, int K)
{
    extern __shared__ float sm[];
    float* As = sm;
    float* Bs = sm + 2 * ASZ;

    const int tid  = threadIdx.x;
    const int lane = tid & 31;
    const int warp = tid >> 5;
    const int wm   = warp >> 1;
    const int wn   = warp & 1;
    const int lr   = lane >> 2;
    const int lc   = lane & 3;
    const int row0 = blockIdx.y << 7;
    const int col0 = blockIdx.x << 7;

    const int ar = tid >> 3;
    const int ac = (tid & 7) << 2;
    const int br = tid >> 5;
    const int bc = (tid & 31) << 2;

    float acc[2][8][4];
#pragma unroll
    for (int mi = 0; mi < 2; ++mi)
#pragma unroll
        for (int ni = 0; ni < 8; ++ni)
#pragma unroll
            for (int r = 0; r < 4; ++r) acc[mi][ni][r] = 0.f;

    const int nch = K >> 5;
    {
        const float* Ag = A + (size_t)(row0 + ar) * K + ac;
        const float* Bg = Bm + (size_t)br * N + col0 + bc;
#pragma unroll
        for (int it = 0; it < 4; ++it)
            cpa16(As + (ar + it * 32) * ASTR + ac, Ag + (size_t)(it * 32) * K);
#pragma unroll
        for (int it = 0; it < 4; ++it)
            cpa16(Bs + (br + it * 8) * BSTR + bc, Bg + (size_t)(it * 8) * N);
        cpa_commit();
    }

    for (int c = 0; c < nch; ++c) {
        cpa_wait0();
        __syncthreads();

        const int cb = c & 1;
        if (c + 1 < nch) {
            const int nb = (c + 1) & 1;
            const int k0 = (c + 1) << 5;
            const float* Ag = A + (size_t)(row0 + ar) * K + k0 + ac;
            const float* Bg = Bm + (size_t)(k0 + br) * N + col0 + bc;
#pragma unroll
            for (int it = 0; it < 4; ++it)
                cpa16(As + nb * ASZ + (ar + it * 32) * ASTR + ac,
                      Ag + (size_t)(it * 32) * K);
#pragma unroll
            for (int it = 0; it < 4; ++it)
                cpa16(Bs + nb * BSZ + (br + it * 8) * BSTR + bc,
                      Bg + (size_t)(it * 8) * N);
            cpa_commit();
        }

        const float* as = As + cb * ASZ;
        const float* bs = Bs + cb * BSZ;

#pragma unroll
        for (int kk = 0; kk < 32; kk += 8) {
            uint32_t af[2][4], bf[8][2];
#pragma unroll
            for (int mi = 0; mi < 2; ++mi) {
                const int mrow = (wm << 5) + (mi << 4) + lr;
                const float* ap = as + mrow * ASTR + kk + lc;
                af[mi][0] = f2tf32(ap[0]);
                af[mi][1] = f2tf32(ap[8 * ASTR]);
                af[mi][2] = f2tf32(ap[4]);
                af[mi][3] = f2tf32(ap[8 * ASTR + 4]);
            }
#pragma unroll
            for (int ni = 0; ni < 8; ++ni) {
                const int ncol = (wn << 6) + (ni << 3) + lr;
                const float* bp = bs + (kk + lc) * BSTR + ncol;
                bf[ni][0] = f2tf32(bp[0]);
                bf[ni][1] = f2tf32(bp[4 * BSTR]);
            }
#pragma unroll
            for (int mi = 0; mi < 2; ++mi)
#pragma unroll
                for (int ni = 0; ni < 8; ++ni)
                    MMA_TF32(acc[mi][ni], af[mi], bf[ni][0], bf[ni][1]);
        }
    }

#pragma unroll
    for (int mi = 0; mi < 2; ++mi) {
        const int row = row0 + (wm << 5) + (mi << 4) + lr;
#pragma unroll
        for (int ni = 0; ni < 8; ++ni) {
            const int col = col0 + (wn << 6) + (ni << 3) + (lc << 1);
            const float* cc = acc[mi][ni];
            *(float2*)(C + (size_t)row * N + col)       = make_float2(cc[0], cc[1]);
            *(float2*)(C + (size_t)(row + 8) * N + col) = make_float2(cc[2], cc[3]);
        }
    }
}

// ---------------------------------------------------------------------------
// Tensor-core causal flash attention (tf32 MMA).
// CTA = 128 q-rows x one head. 8 warps, each owns a 16-row stripe.
// K/V tiles of 64 tokens. S and P.V via mma.m16n8k8.tf32.
// smem strides chosen for conflict-free fragment LDS:
//   Q/K/P stride 68 (bank = 4*lr+lc perm), V stride 72 (bank = 8*lc+lr perm).
// P relayout (C-frag -> A-frag) stays within the warp's private rows:
// __syncwarp only.
// ---------------------------------------------------------------------------
#define QSTR 68
#define KSTR 68
#define VSTR 72
#define PSTR 68
#define ATTN_SMEM ((128 * QSTR + 64 * KSTR + 64 * VSTR + 128 * PSTR) * 4)

__global__ __launch_bounds__(256) void attn_tc(const float* __restrict__ qkv,
                                               float* __restrict__ out)
{
    extern __shared__ float smm[];
    float* Qs = smm;                        // [128][QSTR]
    float* Ks = Qs + 128 * QSTR;            // [64][KSTR]  (row = token, col = dim)
    float* Vs = Ks + 64 * KSTR;             // [64][VSTR]  (row = token, col = dim)
    float* Ps = Vs + 64 * VSTR;             // [128][PSTR]

    const int tid  = threadIdx.x;
    const int lane = tid & 31;
    const int warp = tid >> 5;
    const int lr   = lane >> 2;
    const int lc   = lane & 3;
    const int qb   = gridDim.x - 1 - blockIdx.x;   // heavy tiles first
    const int h    = blockIdx.y;
    const int b    = blockIdx.z;
    const int q0   = qb << 7;
    const int wrow = warp << 4;             // warp's row stripe within tile

    const float* bb = qkv + (size_t)b * (T_ * 3 * DM) + h * DH;

    // Q tile [128][64]
    for (int i = tid; i < 128 * 16; i += 256) {
        const int r  = i >> 4;
        const int c4 = (i & 15) << 2;
        *(float4*)(Qs + r * QSTR + c4) =
            *(const float4*)(bb + (size_t)(q0 + r) * (3 * DM) + c4);
    }

    float m0 = -1e30f, m1 = -1e30f, l0 = 0.f, l1 = 0.f;
    float oacc[8][4];
#pragma unroll
    for (int ni = 0; ni < 8; ++ni)
#pragma unroll
        for (int r = 0; r < 4; ++r) oacc[ni][r] = 0.f;

    const int gr0 = q0 + wrow + lr;         // global q row for c0/c1
    const int gr1 = gr0 + 8;                // global q row for c2/c3
    const int nkt = 2 * qb + 2;

    for (int kt = 0; kt < nkt; ++kt) {
        const int k0 = kt << 6;
        __syncthreads();    // prev iter's Ks/Vs reads done (also covers Qs on kt=0)

        for (int i = tid; i < 64 * 16; i += 256) {
            const int r  = i >> 4;
            const int c4 = (i & 15) << 2;
            *(float4*)(Ks + r * KSTR + c4) =
                *(const float4*)(bb + DM + (size_t)(k0 + r) * (3 * DM) + c4);
        }
        for (int i = tid; i < 64 * 16; i += 256) {
            const int r  = i >> 4;
            const int c4 = (i & 15) << 2;
            *(float4*)(Vs + r * VSTR + c4) =
                *(const float4*)(bb + 2 * DM + (size_t)(k0 + r) * (3 * DM) + c4);
        }
        __syncthreads();

        // ---- S = Q @ K^T (16x64 per warp) ----
        float sacc[8][4];
#pragma unroll
        for (int ni = 0; ni < 8; ++ni)
#pragma unroll
            for (int r = 0; r < 4; ++r) sacc[ni][r] = 0.f;

#pragma unroll
        for (int kk = 0; kk < 64; kk += 8) {
            uint32_t af[4];
            const float* qp = Qs + (wrow + lr) * QSTR + kk + lc;
            af[0] = f2tf32(qp[0]);
            af[1] = f2tf32(qp[8 * QSTR]);
            af[2] = f2tf32(qp[4]);
            af[3] = f2tf32(qp[8 * QSTR + 4]);
#pragma unroll
            for (int ni = 0; ni < 8; ++ni) {
                const float* kp = Ks + (ni * 8 + lr) * KSTR + kk + lc;
                uint32_t b0 = f2tf32(kp[0]);
                uint32_t b1 = f2tf32(kp[4]);
                MMA_TF32(sacc[ni], af, b0, b1);
            }
        }

        // ---- scale + causal mask ----
#pragma unroll
        for (int ni = 0; ni < 8; ++ni)
#pragma unroll
            for (int r = 0; r < 4; ++r) sacc[ni][r] *= 0.125f;

        if (kt >= 2 * qb) {
#pragma unroll
            for (int ni = 0; ni < 8; ++ni) {
                const int cb = k0 + ni * 8 + (lc << 1);
                if (cb     > gr0) sacc[ni][0] = -1e30f;
                if (cb + 1 > gr0) sacc[ni][1] = -1e30f;
                if (cb     > gr1) sacc[ni][2] = -1e30f;
                if (cb + 1 > gr1) sacc[ni][3] = -1e30f;
            }
        }

        // ---- online softmax (rows lr and lr+8; reduce over quad lanes) ----
        float rm0 = -1e30f, rm1 = -1e30f;
#pragma unroll
        for (int ni = 0; ni < 8; ++ni) {
            rm0 = fmaxf(rm0, fmaxf(sacc[ni][0], sacc[ni][1]));
            rm1 = fmaxf(rm1, fmaxf(sacc[ni][2], sacc[ni][3]));
        }
        rm0 = fmaxf(rm0, __shfl_xor_sync(0xffffffffu, rm0, 1, 4));
        rm0 = fmaxf(rm0, __shfl_xor_sync(0xffffffffu, rm0, 2, 4));
        rm1 = fmaxf(rm1, __shfl_xor_sync(0xffffffffu, rm1, 1, 4));
        rm1 = fmaxf(rm1, __shfl_xor_sync(0xffffffffu, rm1, 2, 4));

        const float mn0 = fmaxf(m0, rm0);
        const float mn1 = fmaxf(m1, rm1);
        const float c0f = __expf(m0 - mn0);
        const float c1f = __expf(m1 - mn1);
        m0 = mn0; m1 = mn1;

        float rs0 = 0.f, rs1 = 0.f;
#pragma unroll
        for (int ni = 0; ni < 8; ++ni) {
            sacc[ni][0] = __expf(sacc[ni][0] - mn0);
            sacc[ni][1] = __expf(sacc[ni][1] - mn0);
            sacc[ni][2] = __expf(sacc[ni][2] - mn1);
            sacc[ni][3] = __expf(sacc[ni][3] - mn1);
            rs0 += sacc[ni][0] + sacc[ni][1];
            rs1 += sacc[ni][2] + sacc[ni][3];
        }
        rs0 += __shfl_xor_sync(0xffffffffu, rs0, 1, 4);
        rs0 += __shfl_xor_sync(0xffffffffu, rs0, 2, 4);
        rs1 += __shfl_xor_sync(0xffffffffu, rs1, 1, 4);
        rs1 += __shfl_xor_sync(0xffffffffu, rs1, 2, 4);
        l0 = l0 * c0f + rs0;
        l1 = l1 * c1f + rs1;
#pragma unroll
        for (int ni = 0; ni < 8; ++ni) {
            oacc[ni][0] *= c0f; oacc[ni][1] *= c0f;
            oacc[ni][2] *= c1f; oacc[ni][3] *= c1f;
        }

        // ---- stage P (C-frag -> smem), warp-private rows ----
        {
            float* pr = Ps + (wrow + lr) * PSTR + (lc << 1);
#pragma unroll
            for (int ni = 0; ni < 8; ++ni) {
                *(float2*)(pr + ni * 8) =
                    make_float2(sacc[ni][0], sacc[ni][1]);
                *(float2*)(pr + 8 * PSTR + ni * 8) =
                    make_float2(sacc[ni][2], sacc[ni][3]);
            }
        }
        __syncwarp();

        // ---- O += P @ V ----
#pragma unroll
        for (int kk = 0; kk < 64; kk += 8) {
            uint32_t af[4];
            const float* pp = Ps + (wrow + lr) * PSTR + kk + lc;
            af[0] = f2tf32(pp[0]);
            af[1] = f2tf32(pp[8 * PSTR]);
            af[2] = f2tf32(pp[4]);
            af[3] = f2tf32(pp[8 * PSTR + 4]);
#pragma unroll
            for (int ni = 0; ni < 8; ++ni) {
                const float* vp = Vs + (kk + lc) * VSTR + ni * 8 + lr;
                uint32_t b0 = f2tf32(vp[0]);
                uint32_t b1 = f2tf32(vp[4 * VSTR]);
                MMA_TF32(oacc[ni], af, b0, b1);
            }
        }
        __syncwarp();   // P reads done before next iter's stores
    }

    // ---- epilogue ----
    const float inv0 = 1.f / l0;
    const float inv1 = 1.f / l1;
    float* ob = out + (size_t)(b * T_ + gr0) * DM + h * DH + (lc << 1);
#pragma unroll
    for (int ni = 0; ni < 8; ++ni) {
        *(float2*)(ob + ni * 8) =
            make_float2(oacc[ni][0] * inv0, oacc[ni][1] * inv0);
        *(float2*)(ob + (size_t)8 * DM + ni * 8) =
            make_float2(oacc[ni][2] * inv1, oacc[ni][3] * inv1);
    }
}

// ---------------------------------------------------------------------------
extern "C" void kernel_launch(void* const* d_in, const int* in_sizes, int n_in,
                              void* d_out, int out_size)
{
    const float* x     = (const float*)d_in[0];
    const float* w_qkv = (const float*)d_in[1];
    const float* w_out = (const float*)d_in[2];
    float* out = (float*)d_out;

    float *qkv, *attn;
    cudaGetSymbolAddress((void**)&qkv,  g_qkv);
    cudaGetSymbolAddress((void**)&attn, g_attn);

    cudaFuncSetAttribute(tf32_gemm,
                         cudaFuncAttributeMaxDynamicSharedMemorySize, GEMM_SMEM);
    cudaFuncSetAttribute(attn_tc,
                         cudaFuncAttributeMaxDynamicSharedMemorySize, ATTN_SMEM);

    // 1) qkv = x @ w_qkv  (tf32 TC)
    tf32_gemm<<<dim3((3 * DM) / 128, NTOK / 128), 256, GEMM_SMEM>>>(
        x, w_qkv, qkv, NTOK, 3 * DM, DM);
    // 2) causal flash attention (tf32 TC)
    attn_tc<<<dim3(T_ / 128, H_, B_), 256, ATTN_SMEM>>>(qkv, attn);
    // 3) out = attn @ w_out  (tf32 TC)
    tf32_gemm<<<dim3(DM / 128, NTOK / 128), 256, GEMM_SMEM>>>(
        attn, w_out, out, NTOK, DM, DM);
}

// round 6
// speedup vs baseline: 2.3188x; 1.0287x over previous
#include <cuda_runtime.h>
#include <cstdint>
#include <cstddef>

#define B_   4
#define T_   2048
#define DM   1024
#define H_   16
#define DH   64
#define NTOK (B_ * T_)   // 8192

// Scratch (allocation-free rule: __device__ globals)
__device__ float g_qkv[(size_t)NTOK * 3 * DM];
__device__ float g_attn[(size_t)NTOK * DM];

__device__ __forceinline__ void cpa16(float* s, const float* g) {
    uint32_t sa = (uint32_t)__cvta_generic_to_shared(s);
    asm volatile("cp.async.cg.shared.global [%0], [%1], 16;\n" :: "r"(sa), "l"(g));
}
__device__ __forceinline__ void cpa_commit() {
    asm volatile("cp.async.commit_group;\n");
}
__device__ __forceinline__ void cpa_wait0() {
    asm volatile("cp.async.wait_group 0;\n");
}
__device__ __forceinline__ uint32_t f2tf32(float x) {
    uint32_t r;
    asm("cvt.rna.tf32.f32 %0, %1;" : "=r"(r) : "f"(x));
    return r;
}
__device__ __forceinline__ uint4 cvt4(float4 v) {
    uint4 u;
    u.x = f2tf32(v.x); u.y = f2tf32(v.y);
    u.z = f2tf32(v.z); u.w = f2tf32(v.w);
    return u;
}
#define MMA_TF32(CC, AF, B0, B1)                                              \
    asm volatile(                                                             \
        "mma.sync.aligned.m16n8k8.row.col.f32.tf32.tf32.f32 "                 \
        "{%0,%1,%2,%3}, {%4,%5,%6,%7}, {%8,%9}, {%0,%1,%2,%3};"               \
        : "+f"((CC)[0]), "+f"((CC)[1]), "+f"((CC)[2]), "+f"((CC)[3])          \
        : "r"((AF)[0]), "r"((AF)[1]), "r"((AF)[2]), "r"((AF)[3]),             \
          "r"(B0), "r"(B1))

// ---------------------------------------------------------------------------
// TF32 tensor-core GEMM: 128x128 CTA tile, k-chunk 32, 256 threads,
// cp.async double buffer. After each chunk lands, an in-place pass converts
// it to tf32 bit patterns so the MMA mainloop is pure LDS+MMA (no cvt).
// ---------------------------------------------------------------------------
#define ASTR 36
#define BSTR 136
#define ASZ  (128 * ASTR)
#define BSZ  (32 * BSTR)
#define GEMM_SMEM ((2 * ASZ + 2 * BSZ) * 4)

__global__ __launch_bounds__(256) void tf32_gemm(const float* __restrict__ A,
                                                 const float* __restrict__ Bm,
                                                 float* __restrict__ C,
                                                 int M, int N, int K)
{
    extern __shared__ float sm[];
    float* As = sm;
    float* Bs = sm + 2 * ASZ;

    const int tid  = threadIdx.x;
    const int lane = tid & 31;
    const int warp = tid >> 5;
    const int wm   = warp >> 1;
    const int wn   = warp & 1;
    const int lr   = lane >> 2;
    const int lc   = lane & 3;
    const int row0 = blockIdx.y << 7;
    const int col0 = blockIdx.x << 7;

    const int ar = tid >> 3;
    const int ac = (tid & 7) << 2;
    const int br = tid >> 5;
    const int bc = (tid & 31) << 2;

    float acc[2][8][4];
#pragma unroll
    for (int mi = 0; mi < 2; ++mi)
#pragma unroll
        for (int ni = 0; ni < 8; ++ni)
#pragma unroll
            for (int r = 0; r < 4; ++r) acc[mi][ni][r] = 0.f;

    const int nch = K >> 5;
    {
        const float* Ag = A + (size_t)(row0 + ar) * K + ac;
        const float* Bg = Bm + (size_t)br * N + col0 + bc;
#pragma unroll
        for (int it = 0; it < 4; ++it)
            cpa16(As + (ar + it * 32) * ASTR + ac, Ag + (size_t)(it * 32) * K);
#pragma unroll
        for (int it = 0; it < 4; ++it)
            cpa16(Bs + (br + it * 8) * BSTR + bc, Bg + (size_t)(it * 8) * N);
        cpa_commit();
    }

    for (int c = 0; c < nch; ++c) {
        cpa_wait0();
        __syncthreads();

        const int cb = c & 1;
        if (c + 1 < nch) {
            const int nb = (c + 1) & 1;
            const int k0 = (c + 1) << 5;
            const float* Ag = A + (size_t)(row0 + ar) * K + k0 + ac;
            const float* Bg = Bm + (size_t)(k0 + br) * N + col0 + bc;
#pragma unroll
            for (int it = 0; it < 4; ++it)
                cpa16(As + nb * ASZ + (ar + it * 32) * ASTR + ac,
                      Ag + (size_t)(it * 32) * K);
#pragma unroll
            for (int it = 0; it < 4; ++it)
                cpa16(Bs + nb * BSZ + (br + it * 8) * BSTR + bc,
                      Bg + (size_t)(it * 8) * N);
            cpa_commit();
        }

        // in-place tf32 conversion of the chunk this thread cp.async'd
        {
            float* ab = As + cb * ASZ;
            float* bb = Bs + cb * BSZ;
#pragma unroll
            for (int it = 0; it < 4; ++it) {
                float4* p = (float4*)(ab + (ar + it * 32) * ASTR + ac);
                *(uint4*)p = cvt4(*p);
            }
#pragma unroll
            for (int it = 0; it < 4; ++it) {
                float4* p = (float4*)(bb + (br + it * 8) * BSTR + bc);
                *(uint4*)p = cvt4(*p);
            }
        }
        __syncthreads();

        const uint32_t* as = (const uint32_t*)(As + cb * ASZ);
        const uint32_t* bs = (const uint32_t*)(Bs + cb * BSZ);

#pragma unroll
        for (int kk = 0; kk < 32; kk += 8) {
            uint32_t af[2][4], bf[8][2];
#pragma unroll
            for (int mi = 0; mi < 2; ++mi) {
                const int mrow = (wm << 5) + (mi << 4) + lr;
                const uint32_t* ap = as + mrow * ASTR + kk + lc;
                af[mi][0] = ap[0];
                af[mi][1] = ap[8 * ASTR];
                af[mi][2] = ap[4];
                af[mi][3] = ap[8 * ASTR + 4];
            }
#pragma unroll
            for (int ni = 0; ni < 8; ++ni) {
                const int ncol = (wn << 6) + (ni << 3) + lr;
                const uint32_t* bp = bs + (kk + lc) * BSTR + ncol;
                bf[ni][0] = bp[0];
                bf[ni][1] = bp[4 * BSTR];
            }
#pragma unroll
            for (int mi = 0; mi < 2; ++mi)
#pragma unroll
                for (int ni = 0; ni < 8; ++ni)
                    MMA_TF32(acc[mi][ni], af[mi], bf[ni][0], bf[ni][1]);
        }
    }

#pragma unroll
    for (int mi = 0; mi < 2; ++mi) {
        const int row = row0 + (wm << 5) + (mi << 4) + lr;
#pragma unroll
        for (int ni = 0; ni < 8; ++ni) {
            const int col = col0 + (wn << 6) + (ni << 3) + (lc << 1);
            const float* cc = acc[mi][ni];
            *(float2*)(C + (size_t)row * N + col)       = make_float2(cc[0], cc[1]);
            *(float2*)(C + (size_t)(row + 8) * N + col) = make_float2(cc[2], cc[3]);
        }
    }
}

// ---------------------------------------------------------------------------
// Tensor-core causal flash attention (tf32 MMA), v2:
// all smem operands stored PRE-CONVERTED to tf32 (Q scaled by 1/8 at load,
// exact exponent shift); inner loops are pure LDS+MMA.
// CTA = 128 q-rows x one head; 8 warps, 16-row stripes; 64-token K/V tiles.
// ---------------------------------------------------------------------------
#define QSTR 68
#define KSTR 68
#define VSTR 72
#define PSTR 68
#define ATTN_SMEM ((128 * QSTR + 64 * KSTR + 64 * VSTR + 128 * PSTR) * 4)

__global__ __launch_bounds__(256) void attn_tc(const float* __restrict__ qkv,
                                               float* __restrict__ out)
{
    extern __shared__ float smm[];
    float* Qs = smm;                        // [128][QSTR]  tf32(Q/8)
    float* Ks = Qs + 128 * QSTR;            // [64][KSTR]   tf32(K)
    float* Vs = Ks + 64 * KSTR;             // [64][VSTR]   tf32(V)
    float* Ps = Vs + 64 * VSTR;             // [128][PSTR]  tf32(P)

    const int tid  = threadIdx.x;
    const int lane = tid & 31;
    const int warp = tid >> 5;
    const int lr   = lane >> 2;
    const int lc   = lane & 3;
    const int qb   = gridDim.x - 1 - blockIdx.x;   // heavy tiles first
    const int h    = blockIdx.y;
    const int b    = blockIdx.z;
    const int q0   = qb << 7;
    const int wrow = warp << 4;

    const float* bb = qkv + (size_t)b * (T_ * 3 * DM) + h * DH;

    // Q tile [128][64], scaled by 1/8 (exact) and converted to tf32
    for (int i = tid; i < 128 * 16; i += 256) {
        const int r  = i >> 4;
        const int c4 = (i & 15) << 2;
        float4 v = *(const float4*)(bb + (size_t)(q0 + r) * (3 * DM) + c4);
        v.x *= 0.125f; v.y *= 0.125f; v.z *= 0.125f; v.w *= 0.125f;
        *(uint4*)(Qs + r * QSTR + c4) = cvt4(v);
    }

    float m0 = -1e30f, m1 = -1e30f, l0 = 0.f, l1 = 0.f;
    float oacc[8][4];
#pragma unroll
    for (int ni = 0; ni < 8; ++ni)
#pragma unroll
        for (int r = 0; r < 4; ++r) oacc[ni][r] = 0.f;

    const int gr0 = q0 + wrow + lr;
    const int gr1 = gr0 + 8;
    const int nkt = 2 * qb + 2;

    for (int kt = 0; kt < nkt; ++kt) {
        const int k0 = kt << 6;
        __syncthreads();    // prev tile's Ks/Vs/Ps reads done (covers Qs on kt=0)

        for (int i = tid; i < 64 * 16; i += 256) {
            const int r  = i >> 4;
            const int c4 = (i & 15) << 2;
            float4 v = *(const float4*)(bb + DM + (size_t)(k0 + r) * (3 * DM) + c4);
            *(uint4*)(Ks + r * KSTR + c4) = cvt4(v);
        }
        for (int i = tid; i < 64 * 16; i += 256) {
            const int r  = i >> 4;
            const int c4 = (i & 15) << 2;
            float4 v = *(const float4*)(bb + 2 * DM + (size_t)(k0 + r) * (3 * DM) + c4);
            *(uint4*)(Vs + r * VSTR + c4) = cvt4(v);
        }
        __syncthreads();

        // ---- S = (Q/8) @ K^T (16x64 per warp), pure LDS+MMA ----
        float sacc[8][4];
#pragma unroll
        for (int ni = 0; ni < 8; ++ni)
#pragma unroll
            for (int r = 0; r < 4; ++r) sacc[ni][r] = 0.f;

#pragma unroll
        for (int kk = 0; kk < 64; kk += 8) {
            uint32_t af[4];
            const uint32_t* qp =
                (const uint32_t*)(Qs + (wrow + lr) * QSTR + kk + lc);
            af[0] = qp[0];
            af[1] = qp[8 * QSTR];
            af[2] = qp[4];
            af[3] = qp[8 * QSTR + 4];
#pragma unroll
            for (int ni = 0; ni < 8; ++ni) {
                const uint32_t* kp =
                    (const uint32_t*)(Ks + (ni * 8 + lr) * KSTR + kk + lc);
                MMA_TF32(sacc[ni], af, kp[0], kp[4]);
            }
        }

        // ---- causal mask (scores already scaled) ----
        if (kt >= 2 * qb) {
#pragma unroll
            for (int ni = 0; ni < 8; ++ni) {
                const int cb = k0 + ni * 8 + (lc << 1);
                if (cb     > gr0) sacc[ni][0] = -1e30f;
                if (cb + 1 > gr0) sacc[ni][1] = -1e30f;
                if (cb     > gr1) sacc[ni][2] = -1e30f;
                if (cb + 1 > gr1) sacc[ni][3] = -1e30f;
            }
        }

        // ---- online softmax (rows lr and lr+8; quad-lane reductions) ----
        float rm0 = -1e30f, rm1 = -1e30f;
#pragma unroll
        for (int ni = 0; ni < 8; ++ni) {
            rm0 = fmaxf(rm0, fmaxf(sacc[ni][0], sacc[ni][1]));
            rm1 = fmaxf(rm1, fmaxf(sacc[ni][2], sacc[ni][3]));
        }
        rm0 = fmaxf(rm0, __shfl_xor_sync(0xffffffffu, rm0, 1, 4));
        rm0 = fmaxf(rm0, __shfl_xor_sync(0xffffffffu, rm0, 2, 4));
        rm1 = fmaxf(rm1, __shfl_xor_sync(0xffffffffu, rm1, 1, 4));
        rm1 = fmaxf(rm1, __shfl_xor_sync(0xffffffffu, rm1, 2, 4));

        const float mn0 = fmaxf(m0, rm0);
        const float mn1 = fmaxf(m1, rm1);
        const float c0f = __expf(m0 - mn0);
        const float c1f = __expf(m1 - mn1);
        m0 = mn0; m1 = mn1;

        float rs0 = 0.f, rs1 = 0.f;
#pragma unroll
        for (int ni = 0; ni < 8; ++ni) {
            sacc[ni][0] = __expf(sacc[ni][0] - mn0);
            sacc[ni][1] = __expf(sacc[ni][1] - mn0);
            sacc[ni][2] = __expf(sacc[ni][2] - mn1);
            sacc[ni][3] = __expf(sacc[ni][3] - mn1);
            rs0 += sacc[ni][0] + sacc[ni][1];
            rs1 += sacc[ni][2] + sacc[ni][3];
        }
        rs0 += __shfl_xor_sync(0xffffffffu, rs0, 1, 4);
        rs0 += __shfl_xor_sync(0xffffffffu, rs0, 2, 4);
        rs1 += __shfl_xor_sync(0xffffffffu, rs1, 1, 4);
        rs1 += __shfl_xor_sync(0xffffffffu, rs1, 2, 4);
        l0 = l0 * c0f + rs0;
        l1 = l1 * c1f + rs1;
#pragma unroll
        for (int ni = 0; ni < 8; ++ni) {
            oacc[ni][0] *= c0f; oacc[ni][1] *= c0f;
            oacc[ni][2] *= c1f; oacc[ni][3] *= c1f;
        }

        // ---- stage P as tf32 (warp-private rows) ----
        {
            float* pr = Ps + (wrow + lr) * PSTR + (lc << 1);
#pragma unroll
            for (int ni = 0; ni < 8; ++ni) {
                *(uint2*)(pr + ni * 8) =
                    make_uint2(f2tf32(sacc[ni][0]), f2tf32(sacc[ni][1]));
                *(uint2*)(pr + 8 * PSTR + ni * 8) =
                    make_uint2(f2tf32(sacc[ni][2]), f2tf32(sacc[ni][3]));
            }
        }
        __syncwarp();

        // ---- O += P @ V, pure LDS+MMA ----
#pragma unroll
        for (int kk = 0; kk < 64; kk += 8) {
            uint32_t af[4];
            const uint32_t* pp =
                (const uint32_t*)(Ps + (wrow + lr) * PSTR + kk + lc);
            af[0] = pp[0];
            af[1] = pp[8 * PSTR];
            af[2] = pp[4];
            af[3] = pp[8 * PSTR + 4];
#pragma unroll
            for (int ni = 0; ni < 8; ++ni) {
                const uint32_t* vp =
                    (const uint32_t*)(Vs + (kk + lc) * VSTR + ni * 8 + lr);
                MMA_TF32(oacc[ni], af, vp[0], vp[4 * VSTR]);
            }
        }
    }

    // ---- epilogue ----
    const float inv0 = 1.f / l0;
    const float inv1 = 1.f / l1;
    float* ob = out + (size_t)(b * T_ + gr0) * DM + h * DH + (lc << 1);
#pragma unroll
    for (int ni = 0; ni < 8; ++ni) {
        *(float2*)(ob + ni * 8) =
            make_float2(oacc[ni][0] * inv0, oacc[ni][1] * inv0);
        *(float2*)(ob + (size_t)8 * DM + ni * 8) =
            make_float2(oacc[ni][2] * inv1, oacc[ni][3] * inv1);
    }
}

// ---------------------------------------------------------------------------
extern "C" void kernel_launch(void* const* d_in, const int* in_sizes, int n_in,
                              void* d_out, int out_size)
{
    const float* x     = (const float*)d_in[0];
    const float* w_qkv = (const float*)d_in[1];
    const float* w_out = (const float*)d_in[2];
    float* out = (float*)d_out;

    float *qkv, *attn;
    cudaGetSymbolAddress((void**)&qkv,  g_qkv);
    cudaGetSymbolAddress((void**)&attn, g_attn);

    cudaFuncSetAttribute(tf32_gemm,
                         cudaFuncAttributeMaxDynamicSharedMemorySize, GEMM_SMEM);
    cudaFuncSetAttribute(attn_tc,
                         cudaFuncAttributeMaxDynamicSharedMemorySize, ATTN_SMEM);

    // 1) qkv = x @ w_qkv  (tf32 TC)
    tf32_gemm<<<dim3((3 * DM) / 128, NTOK / 128), 256, GEMM_SMEM>>>(
        x, w_qkv, qkv, NTOK, 3 * DM, DM);
    // 2) causal flash attention (tf32 TC)
    attn_tc<<<dim3(T_ / 128, H_, B_), 256, ATTN_SMEM>>>(qkv, attn);
    // 3) out = attn @ w_out  (tf32 TC)
    tf32_gemm<<<dim3(DM / 128, NTOK / 128), 256, GEMM_SMEM>>>(
        attn, w_out, out, NTOK, DM, DM);
}

// round 7
// speedup vs baseline: 2.5991x; 1.1209x over previous
#include <cuda_runtime.h>
#include <cstdint>
#include <cstddef>

#define B_   4
#define T_   2048
#define DM   1024
#define H_   16
#define DH   64
#define NTOK (B_ * T_)   // 8192

// Scratch (allocation-free rule: __device__ globals)
__device__ float g_qkv[(size_t)NTOK * 3 * DM];   // tf32-rounded qkv
__device__ float g_xa [(size_t)NTOK * DM];       // tf32(x), later tf32(attn out)
__device__ float g_wq [(size_t)DM * 3 * DM];     // tf32(w_qkv)
__device__ float g_wo [(size_t)DM * DM];         // tf32(w_out)

__device__ __forceinline__ void cpa16(float* s, const float* g) {
    uint32_t sa = (uint32_t)__cvta_generic_to_shared(s);
    asm volatile("cp.async.cg.shared.global [%0], [%1], 16;\n" :: "r"(sa), "l"(g));
}
__device__ __forceinline__ void cpa_commit() {
    asm volatile("cp.async.commit_group;\n");
}
__device__ __forceinline__ void cpa_wait0() {
    asm volatile("cp.async.wait_group 0;\n");
}
__device__ __forceinline__ uint32_t f2tf32(float x) {
    uint32_t r;
    asm("cvt.rna.tf32.f32 %0, %1;" : "=r"(r) : "f"(x));
    return r;
}
__device__ __forceinline__ uint4 cvt4(float4 v) {
    uint4 u;
    u.x = f2tf32(v.x); u.y = f2tf32(v.y);
    u.z = f2tf32(v.z); u.w = f2tf32(v.w);
    return u;
}
__device__ __forceinline__ float ex2(float x) {
    float r;
    asm("ex2.approx.f32 %0, %1;" : "=f"(r) : "f"(x));
    return r;
}
#define MMA_TF32(CC, AF, B0, B1)                                              \
    asm volatile(                                                             \
        "mma.sync.aligned.m16n8k8.row.col.f32.tf32.tf32.f32 "                 \
        "{%0,%1,%2,%3}, {%4,%5,%6,%7}, {%8,%9}, {%0,%1,%2,%3};"               \
        : "+f"((CC)[0]), "+f"((CC)[1]), "+f"((CC)[2]), "+f"((CC)[3])          \
        : "r"((AF)[0]), "r"((AF)[1]), "r"((AF)[2]), "r"((AF)[3]),             \
          "r"(B0), "r"(B1))

// ---------------------------------------------------------------------------
// Pre-pass: round fp32 -> tf32 bit patterns (pure bandwidth).
// ---------------------------------------------------------------------------
__global__ __launch_bounds__(256) void cvt_tf32(const float4* __restrict__ in,
                                                uint4* __restrict__ out)
{
    const size_t i = (size_t)blockIdx.x * 256 + threadIdx.x;
    out[i] = cvt4(in[i]);
}

// ---------------------------------------------------------------------------
// TF32 tensor-core GEMM (R4 structure, inputs pre-rounded => mainloop is pure
// cp.async + LDS + MMA; no cvt, no extra syncs). 128x128 CTA tile, k-chunk 32,
// 256 threads, cp.async double buffer.
// CVTOUT: epilogue rounds C to tf32 bits (for tensors consumed downstream).
// ---------------------------------------------------------------------------
#define ASTR 36
#define BSTR 136
#define ASZ  (128 * ASTR)
#define BSZ  (32 * BSTR)
#define GEMM_SMEM ((2 * ASZ + 2 * BSZ) * 4)

template<bool CVTOUT>
__global__ __launch_bounds__(256) void tf32_gemm(const float* __restrict__ A,
                                                 const float* __restrict__ Bm,
                                                 float* __restrict__ C,
                                                 int M, int N, int K)
{
    extern __shared__ float sm[];
    float* As = sm;
    float* Bs = sm + 2 * ASZ;

    const int tid  = threadIdx.x;
    const int lane = tid & 31;
    const int warp = tid >> 5;
    const int wm   = warp >> 1;
    const int wn   = warp & 1;
    const int lr   = lane >> 2;
    const int lc   = lane & 3;
    const int row0 = blockIdx.y << 7;
    const int col0 = blockIdx.x << 7;

    const int ar = tid >> 3;
    const int ac = (tid & 7) << 2;
    const int br = tid >> 5;
    const int bc = (tid & 31) << 2;

    float acc[2][8][4];
#pragma unroll
    for (int mi = 0; mi < 2; ++mi)
#pragma unroll
        for (int ni = 0; ni < 8; ++ni)
#pragma unroll
            for (int r = 0; r < 4; ++r) acc[mi][ni][r] = 0.f;

    const int nch = K >> 5;
    {
        const float* Ag = A + (size_t)(row0 + ar) * K + ac;
        const float* Bg = Bm + (size_t)br * N + col0 + bc;
#pragma unroll
        for (int it = 0; it < 4; ++it)
            cpa16(As + (ar + it * 32) * ASTR + ac, Ag + (size_t)(it * 32) * K);
#pragma unroll
        for (int it = 0; it < 4; ++it)
            cpa16(Bs + (br + it * 8) * BSTR + bc, Bg + (size_t)(it * 8) * N);
        cpa_commit();
    }

    for (int c = 0; c < nch; ++c) {
        cpa_wait0();
        __syncthreads();

        const int cb = c & 1;
        if (c + 1 < nch) {
            const int nb = (c + 1) & 1;
            const int k0 = (c + 1) << 5;
            const float* Ag = A + (size_t)(row0 + ar) * K + k0 + ac;
            const float* Bg = Bm + (size_t)(k0 + br) * N + col0 + bc;
#pragma unroll
            for (int it = 0; it < 4; ++it)
                cpa16(As + nb * ASZ + (ar + it * 32) * ASTR + ac,
                      Ag + (size_t)(it * 32) * K);
#pragma unroll
            for (int it = 0; it < 4; ++it)
                cpa16(Bs + nb * BSZ + (br + it * 8) * BSTR + bc,
                      Bg + (size_t)(it * 8) * N);
            cpa_commit();
        }

        const uint32_t* as = (const uint32_t*)(As + cb * ASZ);
        const uint32_t* bs = (const uint32_t*)(Bs + cb * BSZ);

#pragma unroll
        for (int kk = 0; kk < 32; kk += 8) {
            uint32_t af[2][4], bf[8][2];
#pragma unroll
            for (int mi = 0; mi < 2; ++mi) {
                const int mrow = (wm << 5) + (mi << 4) + lr;
                const uint32_t* ap = as + mrow * ASTR + kk + lc;
                af[mi][0] = ap[0];
                af[mi][1] = ap[8 * ASTR];
                af[mi][2] = ap[4];
                af[mi][3] = ap[8 * ASTR + 4];
            }
#pragma unroll
            for (int ni = 0; ni < 8; ++ni) {
                const int ncol = (wn << 6) + (ni << 3) + lr;
                const uint32_t* bp = bs + (kk + lc) * BSTR + ncol;
                bf[ni][0] = bp[0];
                bf[ni][1] = bp[4 * BSTR];
            }
#pragma unroll
            for (int mi = 0; mi < 2; ++mi)
#pragma unroll
                for (int ni = 0; ni < 8; ++ni)
                    MMA_TF32(acc[mi][ni], af[mi], bf[ni][0], bf[ni][1]);
        }
    }

#pragma unroll
    for (int mi = 0; mi < 2; ++mi) {
        const int row = row0 + (wm << 5) + (mi << 4) + lr;
#pragma unroll
        for (int ni = 0; ni < 8; ++ni) {
            const int col = col0 + (wn << 6) + (ni << 3) + (lc << 1);
            const float* cc = acc[mi][ni];
            if (CVTOUT) {
                *(uint2*)(C + (size_t)row * N + col) =
                    make_uint2(f2tf32(cc[0]), f2tf32(cc[1]));
                *(uint2*)(C + (size_t)(row + 8) * N + col) =
                    make_uint2(f2tf32(cc[2]), f2tf32(cc[3]));
            } else {
                *(float2*)(C + (size_t)row * N + col) =
                    make_float2(cc[0], cc[1]);
                *(float2*)(C + (size_t)(row + 8) * N + col) =
                    make_float2(cc[2], cc[3]);
            }
        }
    }
}

// ---------------------------------------------------------------------------
// Tensor-core causal flash attention, v3.
// - qkv arrives pre-rounded to tf32: K/V fills are pure LDG+STS (no cvt).
// - K/V stored in MMA-fragment-packed layout: each lane's (b0,b1) pair is
//   one LDS.64; lane rotation (+5*kkb) makes fills near-conflict-free and
//   reads exactly conflict-free.
// - softmax in exp2 domain: Q pre-scaled by 0.125*log2(e); ex2.approx only.
// - Q/P row-major as in R6 (stride 68, conflict-free fragment LDS.32).
// CTA = 128 q-rows x one head; 8 warps, 16-row stripes; 64-token K/V tiles.
// ---------------------------------------------------------------------------
#define QSTR 68
#define PSTR 68
#define ATTN_SMEM ((128 * QSTR + 128 * PSTR + 4096 + 4096) * 4)  // 102400 B

__global__ __launch_bounds__(256) void attn_tc(const float* __restrict__ qkv,
                                               float* __restrict__ out)
{
    extern __shared__ float smm[];
    float* Qs = smm;                        // [128][QSTR] tf32(Q * 0.18034)
    float* Ps = Qs + 128 * QSTR;            // [128][PSTR] tf32(P)
    float* Kf = Ps + 128 * PSTR;            // [4096] fragment-packed K
    float* Vf = Kf + 4096;                  // [4096] fragment-packed V

    const int tid  = threadIdx.x;
    const int lane = tid & 31;
    const int warp = tid >> 5;
    const int lr   = lane >> 2;
    const int lc   = lane & 3;
    const int qb   = gridDim.x - 1 - blockIdx.x;   // heavy tiles first
    const int h    = blockIdx.y;
    const int b    = blockIdx.z;
    const int q0   = qb << 7;
    const int wrow = warp << 4;

    const float* bb = qkv + (size_t)b * (T_ * 3 * DM) + h * DH;

    // Q tile [128][64]: scale by 0.125*log2(e) (exp2-domain softmax), cvt.
    const float QSCALE = 0.1803368867f;     // 0.125 * 1.4426950408
    for (int i = tid; i < 128 * 16; i += 256) {
        const int r  = i >> 4;
        const int c4 = (i & 15) << 2;
        float4 v = *(const float4*)(bb + (size_t)(q0 + r) * (3 * DM) + c4);
        v.x *= QSCALE; v.y *= QSCALE; v.z *= QSCALE; v.w *= QSCALE;
        *(uint4*)(Qs + r * QSTR + c4) = cvt4(v);
    }

    float m0 = -1e30f, m1 = -1e30f, l0 = 0.f, l1 = 0.f;
    float oacc[8][4];
#pragma unroll
    for (int ni = 0; ni < 8; ++ni)
#pragma unroll
        for (int r = 0; r < 4; ++r) oacc[ni][r] = 0.f;

    const int gr0 = q0 + wrow + lr;
    const int gr1 = gr0 + 8;
    const int nkt = 2 * qb + 2;

    for (int kt = 0; kt < nkt; ++kt) {
        const int k0 = kt << 6;
        __syncthreads();    // prev tile's Kf/Vf/Ps reads done (covers Qs kt=0)

        // ---- K fill: fragment-packed. K elem (t,d):
        //   word = (d>>3)*512 + (t>>3)*64 + (((t&7)*4 + (d&3) + 5*(d>>3))&31)*2
        //          + ((d>>2)&1)
        for (int i = tid; i < 64 * 16; i += 256) {
            const int t  = i >> 4;
            const int c4 = (i & 15) << 2;
            float4 v = *(const float4*)(bb + DM + (size_t)(k0 + t) * (3 * DM) + c4);
            const int kkb  = c4 >> 3;
            const int slot = (c4 >> 2) & 1;
            const int base = kkb * 512 + (t >> 3) * 64;
            const int lb   = (t & 7) * 4 + 5 * kkb;
            Kf[base + ((lb + 0) & 31) * 2 + slot] = v.x;
            Kf[base + ((lb + 1) & 31) * 2 + slot] = v.y;
            Kf[base + ((lb + 2) & 31) * 2 + slot] = v.z;
            Kf[base + ((lb + 3) & 31) * 2 + slot] = v.w;
        }
        // ---- V fill: fragment-packed. V elem (t,d):
        //   word = (t>>3)*512 + (d>>3)*64 + (((d&7)*4 + (t&3) + 5*(t>>3))&31)*2
        //          + ((t>>2)&1)
        for (int i = tid; i < 64 * 16; i += 256) {
            const int t  = i >> 4;
            const int c4 = (i & 15) << 2;
            float4 v = *(const float4*)(bb + 2 * DM + (size_t)(k0 + t) * (3 * DM) + c4);
            const int kkb  = t >> 3;
            const int slot = (t >> 2) & 1;
            const int base = kkb * 512 + (c4 >> 3) * 64;
            const int lb   = (c4 & 7) * 4 + (t & 3) + 5 * kkb;
            Vf[base + ((lb + 0) & 31) * 2 + slot] = v.x;
            Vf[base + ((lb + 4) & 31) * 2 + slot] = v.y;
            Vf[base + ((lb + 8) & 31) * 2 + slot] = v.z;
            Vf[base + ((lb + 12) & 31) * 2 + slot] = v.w;
        }
        __syncthreads();

        // ---- S = Q @ K^T (16x64 per warp): LDS.32 A-frag + LDS.64 B-frag ----
        float sacc[8][4];
#pragma unroll
        for (int ni = 0; ni < 8; ++ni)
#pragma unroll
            for (int r = 0; r < 4; ++r) sacc[ni][r] = 0.f;

#pragma unroll
        for (int kkb = 0; kkb < 8; ++kkb) {
            uint32_t af[4];
            const uint32_t* qp =
                (const uint32_t*)(Qs + (wrow + lr) * QSTR + kkb * 8 + lc);
            af[0] = qp[0];
            af[1] = qp[8 * QSTR];
            af[2] = qp[4];
            af[3] = qp[8 * QSTR + 4];
            const int y2 = ((lane + 5 * kkb) & 31) * 2;
            const uint32_t* kb = (const uint32_t*)Kf + kkb * 512 + y2;
#pragma unroll
            for (int ni = 0; ni < 8; ++ni) {
                const uint2 kv = *(const uint2*)(kb + ni * 64);
                MMA_TF32(sacc[ni], af, kv.x, kv.y);
            }
        }

        // ---- causal mask (log2-domain scores, already scaled) ----
        if (kt >= 2 * qb) {
#pragma unroll
            for (int ni = 0; ni < 8; ++ni) {
                const int cb = k0 + ni * 8 + (lc << 1);
                if (cb     > gr0) sacc[ni][0] = -1e30f;
                if (cb + 1 > gr0) sacc[ni][1] = -1e30f;
                if (cb     > gr1) sacc[ni][2] = -1e30f;
                if (cb + 1 > gr1) sacc[ni][3] = -1e30f;
            }
        }

        // ---- online softmax in exp2 domain (quad-lane reductions) ----
        float rm0 = -1e30f, rm1 = -1e30f;
#pragma unroll
        for (int ni = 0; ni < 8; ++ni) {
            rm0 = fmaxf(rm0, fmaxf(sacc[ni][0], sacc[ni][1]));
            rm1 = fmaxf(rm1, fmaxf(sacc[ni][2], sacc[ni][3]));
        }
        rm0 = fmaxf(rm0, __shfl_xor_sync(0xffffffffu, rm0, 1, 4));
        rm0 = fmaxf(rm0, __shfl_xor_sync(0xffffffffu, rm0, 2, 4));
        rm1 = fmaxf(rm1, __shfl_xor_sync(0xffffffffu, rm1, 1, 4));
        rm1 = fmaxf(rm1, __shfl_xor_sync(0xffffffffu, rm1, 2, 4));

        const float mn0 = fmaxf(m0, rm0);
        const float mn1 = fmaxf(m1, rm1);
        const float c0f = ex2(m0 - mn0);
        const float c1f = ex2(m1 - mn1);
        m0 = mn0; m1 = mn1;

        float rs0 = 0.f, rs1 = 0.f;
#pragma unroll
        for (int ni = 0; ni < 8; ++ni) {
            sacc[ni][0] = ex2(sacc[ni][0] - mn0);
            sacc[ni][1] = ex2(sacc[ni][1] - mn0);
            sacc[ni][2] = ex2(sacc[ni][2] - mn1);
            sacc[ni][3] = ex2(sacc[ni][3] - mn1);
            rs0 += sacc[ni][0] + sacc[ni][1];
            rs1 += sacc[ni][2] + sacc[ni][3];
        }
        rs0 += __shfl_xor_sync(0xffffffffu, rs0, 1, 4);
        rs0 += __shfl_xor_sync(0xffffffffu, rs0, 2, 4);
        rs1 += __shfl_xor_sync(0xffffffffu, rs1, 1, 4);
        rs1 += __shfl_xor_sync(0xffffffffu, rs1, 2, 4);
        l0 = l0 * c0f + rs0;
        l1 = l1 * c1f + rs1;
#pragma unroll
        for (int ni = 0; ni < 8; ++ni) {
            oacc[ni][0] *= c0f; oacc[ni][1] *= c0f;
            oacc[ni][2] *= c1f; oacc[ni][3] *= c1f;
        }

        // ---- stage P as tf32 (warp-private rows) ----
        {
            float* pr = Ps + (wrow + lr) * PSTR + (lc << 1);
#pragma unroll
            for (int ni = 0; ni < 8; ++ni) {
                *(uint2*)(pr + ni * 8) =
                    make_uint2(f2tf32(sacc[ni][0]), f2tf32(sacc[ni][1]));
                *(uint2*)(pr + 8 * PSTR + ni * 8) =
                    make_uint2(f2tf32(sacc[ni][2]), f2tf32(sacc[ni][3]));
            }
        }
        __syncwarp();

        // ---- O += P @ V: LDS.32 A-frag + LDS.64 B-frag ----
#pragma unroll
        for (int kkb = 0; kkb < 8; ++kkb) {
            uint32_t af[4];
            const uint32_t* pp =
                (const uint32_t*)(Ps + (wrow + lr) * PSTR + kkb * 8 + lc);
            af[0] = pp[0];
            af[1] = pp[8 * PSTR];
            af[2] = pp[4];
            af[3] = pp[8 * PSTR + 4];
            const int y2 = ((lane + 5 * kkb) & 31) * 2;
            const uint32_t* vb = (const uint32_t*)Vf + kkb * 512 + y2;
#pragma unroll
            for (int ni = 0; ni < 8; ++ni) {
                const uint2 vv = *(const uint2*)(vb + ni * 64);
                MMA_TF32(oacc[ni], af, vv.x, vv.y);
            }
        }
        __syncwarp();   // P reads done before next iter's stores
    }

    // ---- epilogue: write tf32-rounded attn output (consumed by GEMM2) ----
    const float inv0 = 1.f / l0;
    const float inv1 = 1.f / l1;
    float* ob = out + (size_t)(b * T_ + gr0) * DM + h * DH + (lc << 1);
#pragma unroll
    for (int ni = 0; ni < 8; ++ni) {
        *(uint2*)(ob + ni * 8) =
            make_uint2(f2tf32(oacc[ni][0] * inv0), f2tf32(oacc[ni][1] * inv0));
        *(uint2*)(ob + (size_t)8 * DM + ni * 8) =
            make_uint2(f2tf32(oacc[ni][2] * inv1), f2tf32(oacc[ni][3] * inv1));
    }
}

// ---------------------------------------------------------------------------
extern "C" void kernel_launch(void* const* d_in, const int* in_sizes, int n_in,
                              void* d_out, int out_size)
{
    const float* x     = (const float*)d_in[0];
    const float* w_qkv = (const float*)d_in[1];
    const float* w_out = (const float*)d_in[2];
    float* out = (float*)d_out;

    float *qkv, *xa, *wq, *wo;
    cudaGetSymbolAddress((void**)&qkv, g_qkv);
    cudaGetSymbolAddress((void**)&xa,  g_xa);
    cudaGetSymbolAddress((void**)&wq,  g_wq);
    cudaGetSymbolAddress((void**)&wo,  g_wo);

    cudaFuncSetAttribute(tf32_gemm<true>,
                         cudaFuncAttributeMaxDynamicSharedMemorySize, GEMM_SMEM);
    cudaFuncSetAttribute(tf32_gemm<false>,
                         cudaFuncAttributeMaxDynamicSharedMemorySize, GEMM_SMEM);
    cudaFuncSetAttribute(attn_tc,
                         cudaFuncAttributeMaxDynamicSharedMemorySize, ATTN_SMEM);

    // 0) pre-round inputs to tf32 bit patterns
    cvt_tf32<<<(NTOK * DM) / 1024, 256>>>((const float4*)x,     (uint4*)xa);
    cvt_tf32<<<(DM * 3 * DM) / 1024, 256>>>((const float4*)w_qkv, (uint4*)wq);
    cvt_tf32<<<(DM * DM) / 1024, 256>>>((const float4*)w_out,  (uint4*)wo);

    // 1) qkv = x @ w_qkv  (epilogue rounds to tf32 for attention)
    tf32_gemm<true><<<dim3((3 * DM) / 128, NTOK / 128), 256, GEMM_SMEM>>>(
        xa, wq, qkv, NTOK, 3 * DM, DM);
    // 2) causal flash attention (writes tf32-rounded output into xa)
    attn_tc<<<dim3(T_ / 128, H_, B_), 256, ATTN_SMEM>>>(qkv, xa);
    // 3) out = attn @ w_out  (plain fp32 epilogue — final output)
    tf32_gemm<false><<<dim3(DM / 128, NTOK / 128), 256, GEMM_SMEM>>>(
        xa, wo, out, NTOK, DM, DM);
}

// round 8
// speedup vs baseline: 3.3935x; 1.3057x over previous
#include <cuda_runtime.h>
#include <cstdint>
#include <cstddef>

#define B_   4
#define T_   2048
#define DM   1024
#define H_   16
#define DH   64
#define NTOK (B_ * T_)   // 8192

// Scratch (allocation-free rule: __device__ globals)
__device__ float g_qkv[(size_t)NTOK * 3 * DM];   // tf32-rounded qkv
__device__ float g_xa [(size_t)NTOK * DM];       // tf32(x), later tf32(attn out)
__device__ float g_wq [(size_t)DM * 3 * DM];     // tf32(w_qkv)
__device__ float g_wo [(size_t)DM * DM];         // tf32(w_out)

__device__ __forceinline__ void cpa16(float* s, const float* g) {
    uint32_t sa = (uint32_t)__cvta_generic_to_shared(s);
    asm volatile("cp.async.cg.shared.global [%0], [%1], 16;\n" :: "r"(sa), "l"(g));
}
__device__ __forceinline__ void cpa_commit() {
    asm volatile("cp.async.commit_group;\n");
}
__device__ __forceinline__ void cpa_wait0() {
    asm volatile("cp.async.wait_group 0;\n");
}
__device__ __forceinline__ void cpa_wait1() {
    asm volatile("cp.async.wait_group 1;\n");
}
__device__ __forceinline__ uint32_t f2tf32(float x) {
    uint32_t r;
    asm("cvt.rna.tf32.f32 %0, %1;" : "=r"(r) : "f"(x));
    return r;
}
__device__ __forceinline__ uint4 cvt4(float4 v) {
    uint4 u;
    u.x = f2tf32(v.x); u.y = f2tf32(v.y);
    u.z = f2tf32(v.z); u.w = f2tf32(v.w);
    return u;
}
__device__ __forceinline__ float ex2(float x) {
    float r;
    asm("ex2.approx.f32 %0, %1;" : "=f"(r) : "f"(x));
    return r;
}
#define MMA_TF32(CC, AF, B0, B1)                                              \
    asm volatile(                                                             \
        "mma.sync.aligned.m16n8k8.row.col.f32.tf32.tf32.f32 "                 \
        "{%0,%1,%2,%3}, {%4,%5,%6,%7}, {%8,%9}, {%0,%1,%2,%3};"               \
        : "+f"((CC)[0]), "+f"((CC)[1]), "+f"((CC)[2]), "+f"((CC)[3])          \
        : "r"((AF)[0]), "r"((AF)[1]), "r"((AF)[2]), "r"((AF)[3]),             \
          "r"(B0), "r"(B1))

// ---------------------------------------------------------------------------
// Pre-pass: round fp32 -> tf32 bit patterns (pure bandwidth).
// ---------------------------------------------------------------------------
__global__ __launch_bounds__(256) void cvt_tf32(const float4* __restrict__ in,
                                                uint4* __restrict__ out)
{
    const size_t i = (size_t)blockIdx.x * 256 + threadIdx.x;
    out[i] = cvt4(in[i]);
}

// ---------------------------------------------------------------------------
// TF32 tensor-core GEMM (unchanged from R7; inputs pre-rounded => mainloop is
// pure cp.async + LDS + MMA). 128x128 CTA tile, k-chunk 32, 256 threads.
// ---------------------------------------------------------------------------
#define ASTR 36
#define BSTR 136
#define ASZ  (128 * ASTR)
#define BSZ  (32 * BSTR)
#define GEMM_SMEM ((2 * ASZ + 2 * BSZ) * 4)

template<bool CVTOUT>
__global__ __launch_bounds__(256) void tf32_gemm(const float* __restrict__ A,
                                                 const float* __restrict__ Bm,
                                                 float* __restrict__ C,
                                                 int M, int N, int K)
{
    extern __shared__ float sm[];
    float* As = sm;
    float* Bs = sm + 2 * ASZ;

    const int tid  = threadIdx.x;
    const int lane = tid & 31;
    const int warp = tid >> 5;
    const int wm   = warp >> 1;
    const int wn   = warp & 1;
    const int lr   = lane >> 2;
    const int lc   = lane & 3;
    const int row0 = blockIdx.y << 7;
    const int col0 = blockIdx.x << 7;

    const int ar = tid >> 3;
    const int ac = (tid & 7) << 2;
    const int br = tid >> 5;
    const int bc = (tid & 31) << 2;

    float acc[2][8][4];
#pragma unroll
    for (int mi = 0; mi < 2; ++mi)
#pragma unroll
        for (int ni = 0; ni < 8; ++ni)
#pragma unroll
            for (int r = 0; r < 4; ++r) acc[mi][ni][r] = 0.f;

    const int nch = K >> 5;
    {
        const float* Ag = A + (size_t)(row0 + ar) * K + ac;
        const float* Bg = Bm + (size_t)br * N + col0 + bc;
#pragma unroll
        for (int it = 0; it < 4; ++it)
            cpa16(As + (ar + it * 32) * ASTR + ac, Ag + (size_t)(it * 32) * K);
#pragma unroll
        for (int it = 0; it < 4; ++it)
            cpa16(Bs + (br + it * 8) * BSTR + bc, Bg + (size_t)(it * 8) * N);
        cpa_commit();
    }

    for (int c = 0; c < nch; ++c) {
        cpa_wait0();
        __syncthreads();

        const int cb = c & 1;
        if (c + 1 < nch) {
            const int nb = (c + 1) & 1;
            const int k0 = (c + 1) << 5;
            const float* Ag = A + (size_t)(row0 + ar) * K + k0 + ac;
            const float* Bg = Bm + (size_t)(k0 + br) * N + col0 + bc;
#pragma unroll
            for (int it = 0; it < 4; ++it)
                cpa16(As + nb * ASZ + (ar + it * 32) * ASTR + ac,
                      Ag + (size_t)(it * 32) * K);
#pragma unroll
            for (int it = 0; it < 4; ++it)
                cpa16(Bs + nb * BSZ + (br + it * 8) * BSTR + bc,
                      Bg + (size_t)(it * 8) * N);
            cpa_commit();
        }

        const uint32_t* as = (const uint32_t*)(As + cb * ASZ);
        const uint32_t* bs = (const uint32_t*)(Bs + cb * BSZ);

#pragma unroll
        for (int kk = 0; kk < 32; kk += 8) {
            uint32_t af[2][4], bf[8][2];
#pragma unroll
            for (int mi = 0; mi < 2; ++mi) {
                const int mrow = (wm << 5) + (mi << 4) + lr;
                const uint32_t* ap = as + mrow * ASTR + kk + lc;
                af[mi][0] = ap[0];
                af[mi][1] = ap[8 * ASTR];
                af[mi][2] = ap[4];
                af[mi][3] = ap[8 * ASTR + 4];
            }
#pragma unroll
            for (int ni = 0; ni < 8; ++ni) {
                const int ncol = (wn << 6) + (ni << 3) + lr;
                const uint32_t* bp = bs + (kk + lc) * BSTR + ncol;
                bf[ni][0] = bp[0];
                bf[ni][1] = bp[4 * BSTR];
            }
#pragma unroll
            for (int mi = 0; mi < 2; ++mi)
#pragma unroll
                for (int ni = 0; ni < 8; ++ni)
                    MMA_TF32(acc[mi][ni], af[mi], bf[ni][0], bf[ni][1]);
        }
    }

#pragma unroll
    for (int mi = 0; mi < 2; ++mi) {
        const int row = row0 + (wm << 5) + (mi << 4) + lr;
#pragma unroll
        for (int ni = 0; ni < 8; ++ni) {
            const int col = col0 + (wn << 6) + (ni << 3) + (lc << 1);
            const float* cc = acc[mi][ni];
            if (CVTOUT) {
                *(uint2*)(C + (size_t)row * N + col) =
                    make_uint2(f2tf32(cc[0]), f2tf32(cc[1]));
                *(uint2*)(C + (size_t)(row + 8) * N + col) =
                    make_uint2(f2tf32(cc[2]), f2tf32(cc[3]));
            } else {
                *(float2*)(C + (size_t)row * N + col) =
                    make_float2(cc[0], cc[1]);
                *(float2*)(C + (size_t)(row + 8) * N + col) =
                    make_float2(cc[2], cc[3]);
            }
        }
    }
}

// ---------------------------------------------------------------------------
// Tensor-core causal flash attention, v4 (latency-focused):
// - cp.async DOUBLE-BUFFERED K/V tiles (row-major padded; tile kt+1 streams
//   while kt computes) — removes the exposed LDG fill latency of v3.
// - Q fragments held in REGISTERS across the whole kt loop (loaded once);
//   the Q smem region is then reused for P staging (smem stays 2-CTA/SM).
// - exp2-domain softmax (Q pre-scaled by 0.125*log2 e), pre-rounded qkv.
// Layouts: K stride 68 (bank 4*lr+lc perm), V stride 72 (bank 8*lc+lr perm),
// P stride 68 — all fragment accesses conflict-free.
// CTA = 128 q-rows x one head; 8 warps, 16-row stripes; 64-token K/V tiles.
// ---------------------------------------------------------------------------
#define KSTR 68
#define VSTR 72
#define PSTR 68
// Ps (=Q staging) + 2*K + 2*V
#define ATTN_SMEM ((128 * PSTR + 2 * 64 * KSTR + 2 * 64 * VSTR) * 4)  // 106496

__global__ __launch_bounds__(256, 2) void attn_tc(const float* __restrict__ qkv,
                                                  float* __restrict__ out)
{
    extern __shared__ float smm[];
    float* Ps = smm;                        // [128][PSTR]: Q staging, then P
    float* K0 = Ps + 128 * PSTR;            // [64][KSTR] buf 0
    float* K1 = K0 + 64 * KSTR;             // [64][KSTR] buf 1
    float* V0 = K1 + 64 * KSTR;             // [64][VSTR] buf 0
    float* V1 = V0 + 64 * VSTR;             // [64][VSTR] buf 1

    const int tid  = threadIdx.x;
    const int lane = tid & 31;
    const int warp = tid >> 5;
    const int lr   = lane >> 2;
    const int lc   = lane & 3;
    const int qb   = gridDim.x - 1 - blockIdx.x;   // heavy tiles first
    const int h    = blockIdx.y;
    const int b    = blockIdx.z;
    const int q0   = qb << 7;
    const int wrow = warp << 4;

    const float* bb = qkv + (size_t)b * (T_ * 3 * DM) + h * DH;

    // per-thread cp.async indices for K/V tiles (64 rows x 16 float4)
    const int fr  = tid >> 4;               // 0..15 (+16 per iter)
    const int fc4 = (tid & 15) << 2;        // 0,4,...,60

    // ---- prologue: start streaming tile 0 while we prep Q ----
    {
        const float* kg = bb + DM     + (size_t)fr * (3 * DM) + fc4;
        const float* vg = bb + 2 * DM + (size_t)fr * (3 * DM) + fc4;
#pragma unroll
        for (int it = 0; it < 4; ++it) {
            cpa16(K0 + (fr + it * 16) * KSTR + fc4,
                  kg + (size_t)(it * 16) * (3 * DM));
            cpa16(V0 + (fr + it * 16) * VSTR + fc4,
                  vg + (size_t)(it * 16) * (3 * DM));
        }
        cpa_commit();
    }

    // ---- Q tile into Ps region: scale by 0.125*log2(e), cvt to tf32 ----
    const float QSCALE = 0.1803368867f;
    for (int i = tid; i < 128 * 16; i += 256) {
        const int r  = i >> 4;
        const int c4 = (i & 15) << 2;
        float4 v = *(const float4*)(bb + (size_t)(q0 + r) * (3 * DM) + c4);
        v.x *= QSCALE; v.y *= QSCALE; v.z *= QSCALE; v.w *= QSCALE;
        *(uint4*)(Ps + r * PSTR + c4) = cvt4(v);
    }
    __syncthreads();

    // ---- hoist Q fragments to registers (warp-private rows) ----
    uint32_t qf[8][4];
#pragma unroll
    for (int kkb = 0; kkb < 8; ++kkb) {
        const uint32_t* qp =
            (const uint32_t*)(Ps + (wrow + lr) * PSTR + kkb * 8 + lc);
        qf[kkb][0] = qp[0];
        qf[kkb][1] = qp[8 * PSTR];
        qf[kkb][2] = qp[4];
        qf[kkb][3] = qp[8 * PSTR + 4];
    }

    float m0 = -1e30f, m1 = -1e30f, l0 = 0.f, l1 = 0.f;
    float oacc[8][4];
#pragma unroll
    for (int ni = 0; ni < 8; ++ni)
#pragma unroll
        for (int r = 0; r < 4; ++r) oacc[ni][r] = 0.f;

    const int gr0 = q0 + wrow + lr;
    const int gr1 = gr0 + 8;
    const int nkt = 2 * qb + 2;

    for (int kt = 0; kt < nkt; ++kt) {
        const int cur = kt & 1;
        // stream next tile into the other buffer
        if (kt + 1 < nkt) {
            float* Kn = (cur ? K0 : K1);
            float* Vn = (cur ? V0 : V1);
            const int kn0 = (kt + 1) << 6;
            const float* kg = bb + DM     + (size_t)(kn0 + fr) * (3 * DM) + fc4;
            const float* vg = bb + 2 * DM + (size_t)(kn0 + fr) * (3 * DM) + fc4;
#pragma unroll
            for (int it = 0; it < 4; ++it) {
                cpa16(Kn + (fr + it * 16) * KSTR + fc4,
                      kg + (size_t)(it * 16) * (3 * DM));
                cpa16(Vn + (fr + it * 16) * VSTR + fc4,
                      vg + (size_t)(it * 16) * (3 * DM));
            }
            cpa_commit();
            cpa_wait1();     // current tile landed; next still in flight
        } else {
            cpa_wait0();
        }
        __syncthreads();

        const float* Ks = cur ? K1 : K0;
        const float* Vs = cur ? V1 : V0;

        // ---- S = Q @ K^T (16x64 per warp) ----
        float sacc[8][4];
#pragma unroll
        for (int ni = 0; ni < 8; ++ni)
#pragma unroll
            for (int r = 0; r < 4; ++r) sacc[ni][r] = 0.f;

#pragma unroll
        for (int kkb = 0; kkb < 8; ++kkb) {
#pragma unroll
            for (int ni = 0; ni < 8; ++ni) {
                const uint32_t* kp =
                    (const uint32_t*)(Ks + (ni * 8 + lr) * KSTR + kkb * 8 + lc);
                MMA_TF32(sacc[ni], qf[kkb], kp[0], kp[4]);
            }
        }

        // ---- causal mask ----
        if (kt >= 2 * qb) {
            const int k0 = kt << 6;
#pragma unroll
            for (int ni = 0; ni < 8; ++ni) {
                const int cb = k0 + ni * 8 + (lc << 1);
                if (cb     > gr0) sacc[ni][0] = -1e30f;
                if (cb + 1 > gr0) sacc[ni][1] = -1e30f;
                if (cb     > gr1) sacc[ni][2] = -1e30f;
                if (cb + 1 > gr1) sacc[ni][3] = -1e30f;
            }
        }

        // ---- online softmax in exp2 domain (quad-lane reductions) ----
        float rm0 = -1e30f, rm1 = -1e30f;
#pragma unroll
        for (int ni = 0; ni < 8; ++ni) {
            rm0 = fmaxf(rm0, fmaxf(sacc[ni][0], sacc[ni][1]));
            rm1 = fmaxf(rm1, fmaxf(sacc[ni][2], sacc[ni][3]));
        }
        rm0 = fmaxf(rm0, __shfl_xor_sync(0xffffffffu, rm0, 1, 4));
        rm0 = fmaxf(rm0, __shfl_xor_sync(0xffffffffu, rm0, 2, 4));
        rm1 = fmaxf(rm1, __shfl_xor_sync(0xffffffffu, rm1, 1, 4));
        rm1 = fmaxf(rm1, __shfl_xor_sync(0xffffffffu, rm1, 2, 4));

        const float mn0 = fmaxf(m0, rm0);
        const float mn1 = fmaxf(m1, rm1);
        const float c0f = ex2(m0 - mn0);
        const float c1f = ex2(m1 - mn1);
        m0 = mn0; m1 = mn1;

        float rs0 = 0.f, rs1 = 0.f;
#pragma unroll
        for (int ni = 0; ni < 8; ++ni) {
            sacc[ni][0] = ex2(sacc[ni][0] - mn0);
            sacc[ni][1] = ex2(sacc[ni][1] - mn0);
            sacc[ni][2] = ex2(sacc[ni][2] - mn1);
            sacc[ni][3] = ex2(sacc[ni][3] - mn1);
            rs0 += sacc[ni][0] + sacc[ni][1];
            rs1 += sacc[ni][2] + sacc[ni][3];
        }
        rs0 += __shfl_xor_sync(0xffffffffu, rs0, 1, 4);
        rs0 += __shfl_xor_sync(0xffffffffu, rs0, 2, 4);
        rs1 += __shfl_xor_sync(0xffffffffu, rs1, 1, 4);
        rs1 += __shfl_xor_sync(0xffffffffu, rs1, 2, 4);
        l0 = l0 * c0f + rs0;
        l1 = l1 * c1f + rs1;
#pragma unroll
        for (int ni = 0; ni < 8; ++ni) {
            oacc[ni][0] *= c0f; oacc[ni][1] *= c0f;
            oacc[ni][2] *= c1f; oacc[ni][3] *= c1f;
        }

        // ---- stage P as tf32 (warp-private rows of Ps) ----
        {
            float* pr = Ps + (wrow + lr) * PSTR + (lc << 1);
#pragma unroll
            for (int ni = 0; ni < 8; ++ni) {
                *(uint2*)(pr + ni * 8) =
                    make_uint2(f2tf32(sacc[ni][0]), f2tf32(sacc[ni][1]));
                *(uint2*)(pr + 8 * PSTR + ni * 8) =
                    make_uint2(f2tf32(sacc[ni][2]), f2tf32(sacc[ni][3]));
            }
        }
        __syncwarp();

        // ---- O += P @ V ----
#pragma unroll
        for (int kkb = 0; kkb < 8; ++kkb) {
            uint32_t af[4];
            const uint32_t* pp =
                (const uint32_t*)(Ps + (wrow + lr) * PSTR + kkb * 8 + lc);
            af[0] = pp[0];
            af[1] = pp[8 * PSTR];
            af[2] = pp[4];
            af[3] = pp[8 * PSTR + 4];
#pragma unroll
            for (int ni = 0; ni < 8; ++ni) {
                const uint32_t* vp =
                    (const uint32_t*)(Vs + (kkb * 8 + lc) * VSTR + ni * 8 + lr);
                MMA_TF32(oacc[ni], af, vp[0], vp[4 * VSTR]);
            }
        }
        __syncthreads();   // K/V/Ps reads done before next prefetch/stores
    }

    // ---- epilogue: write tf32-rounded attn output (consumed by GEMM2) ----
    const float inv0 = 1.f / l0;
    const float inv1 = 1.f / l1;
    float* ob = out + (size_t)(b * T_ + gr0) * DM + h * DH + (lc << 1);
#pragma unroll
    for (int ni = 0; ni < 8; ++ni) {
        *(uint2*)(ob + ni * 8) =
            make_uint2(f2tf32(oacc[ni][0] * inv0), f2tf32(oacc[ni][1] * inv0));
        *(uint2*)(ob + (size_t)8 * DM + ni * 8) =
            make_uint2(f2tf32(oacc[ni][2] * inv1), f2tf32(oacc[ni][3] * inv1));
    }
}

// ---------------------------------------------------------------------------
extern "C" void kernel_launch(void* const* d_in, const int* in_sizes, int n_in,
                              void* d_out, int out_size)
{
    const float* x     = (const float*)d_in[0];
    const float* w_qkv = (const float*)d_in[1];
    const float* w_out = (const float*)d_in[2];
    float* out = (float*)d_out;

    float *qkv, *xa, *wq, *wo;
    cudaGetSymbolAddress((void**)&qkv, g_qkv);
    cudaGetSymbolAddress((void**)&xa,  g_xa);
    cudaGetSymbolAddress((void**)&wq,  g_wq);
    cudaGetSymbolAddress((void**)&wo,  g_wo);

    cudaFuncSetAttribute(tf32_gemm<true>,
                         cudaFuncAttributeMaxDynamicSharedMemorySize, GEMM_SMEM);
    cudaFuncSetAttribute(tf32_gemm<false>,
                         cudaFuncAttributeMaxDynamicSharedMemorySize, GEMM_SMEM);
    cudaFuncSetAttribute(attn_tc,
                         cudaFuncAttributeMaxDynamicSharedMemorySize, ATTN_SMEM);

    // 0) pre-round inputs to tf32 bit patterns
    cvt_tf32<<<(NTOK * DM) / 1024, 256>>>((const float4*)x,       (uint4*)xa);
    cvt_tf32<<<(DM * 3 * DM) / 1024, 256>>>((const float4*)w_qkv, (uint4*)wq);
    cvt_tf32<<<(DM * DM) / 1024, 256>>>((const float4*)w_out,     (uint4*)wo);

    // 1) qkv = x @ w_qkv  (epilogue rounds to tf32 for attention)
    tf32_gemm<true><<<dim3((3 * DM) / 128, NTOK / 128), 256, GEMM_SMEM>>>(
        xa, wq, qkv, NTOK, 3 * DM, DM);
    // 2) causal flash attention (cp.async pipelined; writes tf32 into xa)
    attn_tc<<<dim3(T_ / 128, H_, B_), 256, ATTN_SMEM>>>(qkv, xa);
    // 3) out = attn @ w_out  (plain fp32 epilogue — final output)
    tf32_gemm<false><<<dim3(DM / 128, NTOK / 128), 256, GEMM_SMEM>>>(
        xa, wo, out, NTOK, DM, DM);
}